// round 9
// baseline (speedup 1.0000x reference)
#include <cuda_runtime.h>
#include <cuda_fp16.h>
#include <cstdint>

#define B_ 16
#define S_ 1024
#define E_ 512
#define H_ 8
#define D_ 64
#define L_ 4
#define M_ (B_*S_)   // 16384 rows

// ---------------- device scratch (no allocations allowed) ----------------
__device__ __half g_qh[M_*E_];
__device__ __half g_kh[M_*E_];
__device__ __half g_vh[M_*E_];
__device__ __half g_Qh[M_*E_];
__device__ __half g_Kh[M_*E_];
__device__ __half g_Vh[M_*E_];
__device__ __half g_ctxh[M_*E_];
__device__ __half g_Wqh[E_*E_];
__device__ __half g_Wkh[E_*E_];
__device__ __half g_Wvh[E_*E_];
__device__ __half g_Woh[E_*E_];
__device__ float  g_bv[E_];
__device__ float  g_bo[E_];

// ---------------- PTX helpers ----------------
__device__ __forceinline__ uint32_t smem_u32(const void* p) {
    uint32_t a;
    asm("{ .reg .u64 t; cvta.to.shared.u64 t, %1; cvt.u32.u64 %0, t; }" : "=r"(a) : "l"(p));
    return a;
}
__device__ __forceinline__ void mma_f16(float* c, const uint32_t* a, const uint32_t* b) {
    asm volatile(
        "mma.sync.aligned.m16n8k16.row.col.f32.f16.f16.f32 "
        "{%0,%1,%2,%3}, {%4,%5,%6,%7}, {%8,%9}, {%0,%1,%2,%3};\n"
        : "+f"(c[0]), "+f"(c[1]), "+f"(c[2]), "+f"(c[3])
        : "r"(a[0]), "r"(a[1]), "r"(a[2]), "r"(a[3]), "r"(b[0]), "r"(b[1]));
}
__device__ __forceinline__ void ldsm4(uint32_t& r0, uint32_t& r1, uint32_t& r2, uint32_t& r3,
                                      uint32_t addr) {
    asm volatile("ldmatrix.sync.aligned.m8n8.x4.shared.b16 {%0,%1,%2,%3}, [%4];\n"
                 : "=r"(r0), "=r"(r1), "=r"(r2), "=r"(r3) : "r"(addr));
}
__device__ __forceinline__ void ldsm4t(uint32_t& r0, uint32_t& r1, uint32_t& r2, uint32_t& r3,
                                       uint32_t addr) {
    asm volatile("ldmatrix.sync.aligned.m8n8.x4.trans.shared.b16 {%0,%1,%2,%3}, [%4];\n"
                 : "=r"(r0), "=r"(r1), "=r"(r2), "=r"(r3) : "r"(addr));
}
__device__ __forceinline__ void cpa16(uint32_t d, const void* s) {
    asm volatile("cp.async.ca.shared.global [%0], [%1], 16;\n" :: "r"(d), "l"(s));
}
#define CP_COMMIT() asm volatile("cp.async.commit_group;\n" ::: "memory")
#define CP_WAIT(N)  asm volatile("cp.async.wait_group %0;\n" :: "n"(N) : "memory")

__device__ __forceinline__ uint32_t h2(float a, float b) {
    __half2 v = __floats2half2_rn(a, b);
    return *(uint32_t*)&v;
}
// pack (lo,hi) to f16x2 then 2^x elementwise
__device__ __forceinline__ uint32_t ex2h2(float lo, float hi) {
    uint32_t p, r;
    asm("cvt.rn.f16x2.f32 %0, %1, %2;" : "=r"(p) : "f"(hi), "f"(lo));
    asm("ex2.approx.f16x2 %0, %1;" : "=r"(r) : "r"(p));
    return r;
}
__device__ __forceinline__ uint2 f4_h4(float4 a) {
    uint2 r;
    r.x = h2(a.x, a.y);
    r.y = h2(a.z, a.w);
    return r;
}

// ---------------- prep: single merged fp32 -> fp16 conversion kernel ----------
// blocks [0, 4096): q/k/v conversion, 8 elements/thread.
// blocks [4096, 4352): weights (+bias).
__global__ __launch_bounds__(256) void prep_all(
        const float* __restrict__ q, const float* __restrict__ k, const float* __restrict__ v,
        const float* __restrict__ Wq, const float* __restrict__ Wk,
        const float* __restrict__ Wv_sh, const float* __restrict__ Wv_sp,
        const float* __restrict__ Wo_sh, const float* __restrict__ Wo_sp,
        const float* __restrict__ bv_sh, const float* __restrict__ bv_sp,
        const float* __restrict__ bo_sh, const float* __restrict__ bo_sp,
        const int* __restrict__ langp) {
    int bid = blockIdx.x;
    if (bid < 4096) {
        int t = bid * 256 + threadIdx.x;      // 1M threads, 8 elts each
        int j = t * 2;                        // float4 index
        uint4 o;
        uint2 a, b;
        a = f4_h4(((const float4*)q)[j]); b = f4_h4(((const float4*)q)[j+1]);
        o.x = a.x; o.y = a.y; o.z = b.x; o.w = b.y;
        ((uint4*)g_qh)[t] = o;
        a = f4_h4(((const float4*)k)[j]); b = f4_h4(((const float4*)k)[j+1]);
        o.x = a.x; o.y = a.y; o.z = b.x; o.w = b.y;
        ((uint4*)g_kh)[t] = o;
        a = f4_h4(((const float4*)v)[j]); b = f4_h4(((const float4*)v)[j+1]);
        o.x = a.x; o.y = a.y; o.z = b.x; o.w = b.y;
        ((uint4*)g_vh)[t] = o;
    } else {
        int lang = langp[0];
        int i = (bid - 4096) * 256 + threadIdx.x;   // 65536 threads, 1 float4 each
        ((uint2*)g_Wqh)[i] = f4_h4(((const float4*)Wq)[i]);
        ((uint2*)g_Wkh)[i] = f4_h4(((const float4*)Wk)[i]);
        size_t so = (size_t)lang * (E_*E_/4);
        float4 s, p;
        s = ((const float4*)Wv_sh)[i];  p = ((const float4*)Wv_sp)[so + i];
        ((uint2*)g_Wvh)[i] = f4_h4(make_float4(s.x*p.x, s.y*p.y, s.z*p.z, s.w*p.w));
        s = ((const float4*)Wo_sh)[i];  p = ((const float4*)Wo_sp)[so + i];
        ((uint2*)g_Woh)[i] = f4_h4(make_float4(s.x*p.x, s.y*p.y, s.z*p.z, s.w*p.w));
        if (i < E_) {
            g_bv[i] = bv_sh[i] + bv_sp[lang*E_ + i];
            g_bo[i] = bo_sh[i] + bo_sp[lang*E_ + i];
        }
    }
}

// ---------------- fp16 GEMM core (3-stage ring, write-ahead 1, ONE sync/iter) --
// 128x128x64 tile, 256 thr = 8 warps (4Mx2N), warp 32x64.
#define BM 128
#define BN 128
#define BKH 64
#define NIT (E_/BKH)          // 8
#define TILE_U4 (BM*8)
#define GNS 3                 // stages; writer d=1 ahead -> reuse distance 2

template<int HALF_OUT>
__device__ __forceinline__ void gemm_core(const __half* __restrict__ A,
                                          const __half* __restrict__ W,
                                          const float* __restrict__ bias,
                                          void* __restrict__ Cv,
                                          int bm, int bn, float cs) {
    extern __shared__ uint4 dsm[];
    uint4* sA = dsm;                    // [GNS][TILE_U4]
    uint4* sB = dsm + GNS*TILE_U4;      // [GNS][TILE_U4]
    const int tid  = threadIdx.x;
    const int wid  = tid >> 5;
    const int lane = tid & 31;
    const int wm   = (wid >> 1) * 32;
    const int wn   = (wid & 1) * 64;
    const int grp  = lane >> 2;
    const int t4   = lane & 3;
    const uint32_t sAb = smem_u32(sA);
    const uint32_t sBb = smem_u32(sB);

    float acc[2][8][4];
    #pragma unroll
    for (int i = 0; i < 2; i++)
        #pragma unroll
        for (int j = 0; j < 8; j++)
            #pragma unroll
            for (int q = 0; q < 4; q++) acc[i][j][q] = 0.f;

    auto load_tile = [&](int it, int buf) {
        #pragma unroll
        for (int v = 0; v < 4; ++v) {
            int c = tid*4 + v;
            int r = c >> 3, ch = c & 7;
            uint32_t off = (uint32_t)(buf*TILE_U4 + r*8 + (ch ^ (r & 7))) * 16u;
            cpa16(sAb + off, (const uint4*)(A + (size_t)(bm + r)*E_ + it*BKH) + ch);
            cpa16(sBb + off, (const uint4*)(W + (size_t)(bn + r)*E_ + it*BKH) + ch);
        }
    };

    load_tile(0, 0); CP_COMMIT();

    for (int it = 0; it < NIT; ++it) {
        if (it + 1 < NIT) {
            load_tile(it + 1, (it + 1) % GNS);
            CP_COMMIT();
            CP_WAIT(1);
        } else {
            CP_WAIT(0);
        }
        __syncthreads();   // single barrier: tile `it` published; reuse dist 2 is safe

        const uint32_t aoff = (uint32_t)((it % GNS)*TILE_U4) * 16u;
        #pragma unroll
        for (int k16 = 0; k16 < 4; ++k16) {
            uint32_t af[2][4];
            #pragma unroll
            for (int mf = 0; mf < 2; ++mf) {
                int row = wm + mf*16 + (lane & 15);
                int ch  = k16*2 + (lane >> 4);
                ldsm4(af[mf][0], af[mf][1], af[mf][2], af[mf][3],
                      sAb + aoff + (uint32_t)(row*8 + (ch ^ (row & 7))) * 16u);
            }
            uint32_t bf[8][2];
            #pragma unroll
            for (int np = 0; np < 4; ++np) {
                int row = wn + np*16 + (lane & 7) + ((lane >> 4) & 1)*8;
                int ch  = k16*2 + ((lane >> 3) & 1);
                ldsm4(bf[2*np][0], bf[2*np][1], bf[2*np+1][0], bf[2*np+1][1],
                      sBb + aoff + (uint32_t)(row*8 + (ch ^ (row & 7))) * 16u);
            }
            #pragma unroll
            for (int mf = 0; mf < 2; ++mf)
                #pragma unroll
                for (int nf = 0; nf < 8; ++nf)
                    mma_f16(acc[mf][nf], af[mf], bf[nf]);
        }
        // no trailing sync: buffer it%GNS is only rewritten at iter it+2's load,
        // and every warp's compute(it) precedes its iter-(it+1) barrier arrival.
    }

    #pragma unroll
    for (int mf = 0; mf < 2; ++mf) {
        #pragma unroll
        for (int nf = 0; nf < 8; ++nf) {
            int r0 = bm + wm + mf*16 + grp;
            int c0 = bn + wn + nf*8 + t4*2;
            float b0 = bias[c0], b1 = bias[c0 + 1];
            if (HALF_OUT) {
                __half* C = (__half*)Cv;
                *(uint32_t*)(C + (size_t)r0*E_ + c0)     = h2((acc[mf][nf][0] + b0)*cs, (acc[mf][nf][1] + b1)*cs);
                *(uint32_t*)(C + (size_t)(r0+8)*E_ + c0) = h2((acc[mf][nf][2] + b0)*cs, (acc[mf][nf][3] + b1)*cs);
            } else {
                float* C = (float*)Cv;
                float2 v0, v1;
                v0.x = acc[mf][nf][0] + b0; v0.y = acc[mf][nf][1] + b1;
                v1.x = acc[mf][nf][2] + b0; v1.y = acc[mf][nf][3] + b1;
                *(float2*)(C + (size_t)r0*E_ + c0)     = v0;
                *(float2*)(C + (size_t)(r0+8)*E_ + c0) = v1;
            }
        }
    }
}

#define GEMM_SMEM (2*GNS*TILE_U4*16)   // 96 KB

// batched QKV projection; z==0 (Q) folds score-scale * log2(e) into the output
__global__ __launch_bounds__(256) void gemm_qkv(const __half* Aq, const __half* Ak, const __half* Av,
                                                const __half* Wq, const __half* Wk, const __half* Wv,
                                                const float* bq, const float* bk, const float* bv,
                                                __half* Cq, __half* Ck, __half* Cvp) {
    const int z = blockIdx.z;
    const __half* A = (z == 0) ? Aq : (z == 1) ? Ak : Av;
    const __half* W = (z == 0) ? Wq : (z == 1) ? Wk : Wv;
    const float*  bb = (z == 0) ? bq : (z == 1) ? bk : bv;
    __half*       C = (z == 0) ? Cq : (z == 1) ? Ck : Cvp;
    float cs = (z == 0) ? 0.015625f * 1.44269504088896f : 1.f;
    gemm_core<1>(A, W, bb, C, blockIdx.y * BM, blockIdx.x * BN, cs);
}

__global__ __launch_bounds__(256) void gemm_out(const __half* __restrict__ A,
                                                const __half* __restrict__ W,
                                                const float* __restrict__ bias,
                                                float* __restrict__ C) {
    gemm_core<0>(A, W, bias, C, blockIdx.y * BM, blockIdx.x * BN, 1.f);
}

// ---------------- fp16 flash attention (4-stage ring, write-ahead 2, ONE sync) -
// Exact softmax in log2 domain; mask folded into S-accumulator init; p=ex2.f16x2;
// denominator via ones-column MMA.
#define KVB_U4 (64*8)                 // one K or V buffer (8 KB)
#define ANS 4                          // stages; writer d=2 ahead -> reuse dist 2
#define ATT_SMEM (2*ANS*KVB_U4*16 + ANS*64*4)   // 64 KB + 1 KB

__global__ __launch_bounds__(256) void attn_h(const __half* __restrict__ Q,
                                              const __half* __restrict__ K,
                                              const __half* __restrict__ V,
                                              const int* __restrict__ mask,
                                              __half* __restrict__ ctx) {
    extern __shared__ uint4 dsm[];
    uint4* sK = dsm;                       // [ANS][KVB_U4]
    uint4* sV = dsm + ANS*KVB_U4;          // [ANS][KVB_U4]
    float* mflag = (float*)(dsm + 2*ANS*KVB_U4);  // [ANS][64]

    const int bh = blockIdx.x;
    const int b  = bh >> 3;
    const int h  = bh & 7;
    const int q0 = blockIdx.y * 128;
    const int tid  = threadIdx.x;
    const int wid  = tid >> 5;
    const int lane = tid & 31;
    const int grp  = lane >> 2;
    const int t4   = lane & 3;
    const int row0 = wid * 16;
    const uint32_t sKb = smem_u32(sK);
    const uint32_t sVb = smem_u32(sV);

    const size_t kvbase = (size_t)b*S_*E_ + (size_t)h*D_;

    auto load_kv = [&](int kt, int buf) {
        const int key0 = kt * 64;
        #pragma unroll
        for (int v = 0; v < 2; ++v) {
            int c = tid*2 + v;
            int r = c >> 3, ch = c & 7;
            uint32_t off = (uint32_t)(buf*KVB_U4 + r*8 + (ch ^ (r & 7))) * 16u;
            cpa16(sKb + off, (const uint4*)(K + kvbase + (size_t)(key0 + r)*E_) + ch);
            cpa16(sVb + off, (const uint4*)(V + kvbase + (size_t)(key0 + r)*E_) + ch);
        }
    };

    // Q fragments in registers for whole kernel (A-operand layout)
    uint32_t qf[4][4];
    const __half* qb = Q + ((size_t)b*S_ + q0 + row0)*E_ + h*D_;
    #pragma unroll
    for (int k16 = 0; k16 < 4; ++k16) {
        qf[k16][0] = *(const uint32_t*)(qb + (size_t)grp*E_     + k16*16 + 2*t4);
        qf[k16][1] = *(const uint32_t*)(qb + (size_t)(grp+8)*E_ + k16*16 + 2*t4);
        qf[k16][2] = *(const uint32_t*)(qb + (size_t)grp*E_     + k16*16 + 2*t4 + 8);
        qf[k16][3] = *(const uint32_t*)(qb + (size_t)(grp+8)*E_ + k16*16 + 2*t4 + 8);
    }

    float oacc[8][4];
    #pragma unroll
    for (int nf = 0; nf < 8; nf++)
        #pragma unroll
        for (int c = 0; c < 4; c++) oacc[nf][c] = 0.f;
    float dacc[4] = {0.f, 0.f, 0.f, 0.f};
    const uint32_t ones2[2] = {0x3C003C00u, 0x3C003C00u};

    load_kv(0, 0); CP_COMMIT();
    load_kv(1, 1); CP_COMMIT();
    int m_cur = (tid < 64) ? mask[b*S_ + tid] : 0;
    int m_nxt = (tid < 64) ? mask[b*S_ + 64 + tid] : 0;

    #define NT (S_/64)
    for (int kt = 0; kt < NT; ++kt) {
        if (kt + 2 < NT) { load_kv(kt + 2, (kt + 2) % ANS); CP_COMMIT(); }
        if (tid < 64) mflag[(kt % ANS)*64 + tid] = m_cur ? 0.f : -60000.f;
        m_cur = m_nxt;
        if (kt + 2 < NT && tid < 64) m_nxt = mask[b*S_ + (kt + 2)*64 + tid];
        if (kt + 2 < NT)      { CP_WAIT(2); }
        else if (kt + 1 < NT) { CP_WAIT(1); }
        else                  { CP_WAIT(0); }
        __syncthreads();   // single barrier per iter

        const uint32_t koff = (uint32_t)((kt % ANS)*KVB_U4) * 16u;
        const float* mf_ = mflag + (kt % ANS)*64;

        // S = Q K^T + maskoff
        float sacc[8][4];
        #pragma unroll
        for (int nf = 0; nf < 8; nf++) {
            float2 mo = *(const float2*)&mf_[nf*8 + 2*t4];
            sacc[nf][0] = mo.x; sacc[nf][1] = mo.y;
            sacc[nf][2] = mo.x; sacc[nf][3] = mo.y;
        }
        #pragma unroll
        for (int k16 = 0; k16 < 4; ++k16) {
            #pragma unroll
            for (int np = 0; np < 4; ++np) {
                uint32_t b0, b1, b2, b3;
                int row = np*16 + (lane & 7) + ((lane >> 4) & 1)*8;
                int ch  = k16*2 + ((lane >> 3) & 1);
                ldsm4(b0, b1, b2, b3, sKb + koff + (uint32_t)(row*8 + (ch ^ (row & 7))) * 16u);
                uint32_t bb0[2] = {b0, b1}, bb1[2] = {b2, b3};
                mma_f16(sacc[2*np],   qf[k16], bb0);
                mma_f16(sacc[2*np+1], qf[k16], bb1);
            }
        }

        // p = 2^s -> PV A-fragments
        uint32_t pf[4][4];
        #pragma unroll
        for (int nf = 0; nf < 8; nf++) {
            pf[nf >> 1][(nf & 1) * 2]     = ex2h2(sacc[nf][0], sacc[nf][1]);
            pf[nf >> 1][(nf & 1) * 2 + 1] = ex2h2(sacc[nf][2], sacc[nf][3]);
        }

        // O += P V ; denominator += P * ones
        #pragma unroll
        for (int k16 = 0; k16 < 4; ++k16) {
            #pragma unroll
            for (int np = 0; np < 4; ++np) {
                uint32_t b0, b1, b2, b3;
                int row = k16*16 + (lane & 7) + ((lane >> 3) & 1)*8;
                int ch  = np*2 + ((lane >> 4) & 1);
                ldsm4t(b0, b1, b2, b3, sVb + koff + (uint32_t)(row*8 + (ch ^ (row & 7))) * 16u);
                uint32_t bb0[2] = {b0, b1}, bb1[2] = {b2, b3};
                mma_f16(oacc[2*np],   pf[k16], bb0);
                mma_f16(oacc[2*np+1], pf[k16], bb1);
            }
            mma_f16(dacc, pf[k16], ones2);
        }
        // no trailing sync (reuse distance 2 via ANS=4, d=2)
    }

    float i0 = 1.f / dacc[0], i1 = 1.f / dacc[2];
    __half* op = ctx + ((size_t)b*S_ + q0 + row0)*E_ + h*D_;
    #pragma unroll
    for (int nf = 0; nf < 8; nf++) {
        int c0 = nf*8 + 2*t4;
        *(uint32_t*)(op + (size_t)grp*E_ + c0)     = h2(oacc[nf][0]*i0, oacc[nf][1]*i0);
        *(uint32_t*)(op + (size_t)(grp+8)*E_ + c0) = h2(oacc[nf][2]*i1, oacc[nf][3]*i1);
    }
}

// ---------------- launch ----------------
extern "C" void kernel_launch(void* const* d_in, const int* in_sizes, int n_in,
                              void* d_out, int out_size) {
    const float* q      = (const float*)d_in[0];
    const float* k      = (const float*)d_in[1];
    const float* v      = (const float*)d_in[2];
    const float* Wq     = (const float*)d_in[3];
    const float* bq     = (const float*)d_in[4];
    const float* Wk     = (const float*)d_in[5];
    const float* bk     = (const float*)d_in[6];
    const float* Wv_sh  = (const float*)d_in[7];
    const float* Wv_sp  = (const float*)d_in[8];
    const float* bv_sh  = (const float*)d_in[9];
    const float* bv_sp  = (const float*)d_in[10];
    const float* Wo_sh  = (const float*)d_in[11];
    const float* Wo_sp  = (const float*)d_in[12];
    const float* bo_sh  = (const float*)d_in[13];
    const float* bo_sp  = (const float*)d_in[14];
    const int*   mask   = (const int*)d_in[15];
    const int*   lang   = (const int*)d_in[16];

    void *pqh, *pkh, *pvh, *pQh, *pKh, *pVh, *pctx;
    void *pWq, *pWk, *pWv, *pWo, *pbv, *pbo;
    cudaGetSymbolAddress(&pqh, g_qh);
    cudaGetSymbolAddress(&pkh, g_kh);
    cudaGetSymbolAddress(&pvh, g_vh);
    cudaGetSymbolAddress(&pQh, g_Qh);
    cudaGetSymbolAddress(&pKh, g_Kh);
    cudaGetSymbolAddress(&pVh, g_Vh);
    cudaGetSymbolAddress(&pctx, g_ctxh);
    cudaGetSymbolAddress(&pWq, g_Wqh);
    cudaGetSymbolAddress(&pWk, g_Wkh);
    cudaGetSymbolAddress(&pWv, g_Wvh);
    cudaGetSymbolAddress(&pWo, g_Woh);
    cudaGetSymbolAddress(&pbv, g_bv);
    cudaGetSymbolAddress(&pbo, g_bo);

    static int attr_set = 0;
    if (!attr_set) {
        cudaFuncSetAttribute(gemm_qkv, cudaFuncAttributeMaxDynamicSharedMemorySize, GEMM_SMEM);
        cudaFuncSetAttribute(gemm_out, cudaFuncAttributeMaxDynamicSharedMemorySize, GEMM_SMEM);
        cudaFuncSetAttribute(attn_h,   cudaFuncAttributeMaxDynamicSharedMemorySize, ATT_SMEM);
        attr_set = 1;
    }

    prep_all<<<4096 + 256, 256>>>(q, k, v, Wq, Wk, Wv_sh, Wv_sp, Wo_sh, Wo_sp,
                                  bv_sh, bv_sp, bo_sh, bo_sp, lang);

    dim3 gq(E_/BN, M_/BM, 3);   // (4, 128, 3)
    gemm_qkv<<<gq, 256, GEMM_SMEM>>>((const __half*)pqh, (const __half*)pkh, (const __half*)pvh,
                                     (const __half*)pWq, (const __half*)pWk, (const __half*)pWv,
                                     bq, bk, (const float*)pbv,
                                     (__half*)pQh, (__half*)pKh, (__half*)pVh);

    attn_h<<<dim3(B_*H_, S_/128), 256, ATT_SMEM>>>((const __half*)pQh, (const __half*)pKh,
                                                   (const __half*)pVh, mask, (__half*)pctx);

    dim3 gg(E_/BN, M_/BM);   // (4, 128)
    gemm_out<<<gg, 256, GEMM_SMEM>>>((const __half*)pctx, (const __half*)pWo,
                                     (const float*)pbo, (float*)d_out);
}

// round 10
// speedup vs baseline: 1.4574x; 1.4574x over previous
#include <cuda_runtime.h>
#include <cuda_fp16.h>
#include <cstdint>

#define B_ 16
#define S_ 1024
#define E_ 512
#define H_ 8
#define D_ 64
#define L_ 4
#define M_ (B_*S_)   // 16384 rows

// ---------------- device scratch (no allocations allowed) ----------------
__device__ __half g_qh[M_*E_];
__device__ __half g_kh[M_*E_];
__device__ __half g_vh[M_*E_];
__device__ __half g_Qh[M_*E_];
__device__ __half g_Kh[M_*E_];
__device__ __half g_Vh[M_*E_];
__device__ __half g_ctxh[M_*E_];
__device__ __half g_Wqh[E_*E_];
__device__ __half g_Wkh[E_*E_];
__device__ __half g_Wvh[E_*E_];
__device__ __half g_Woh[E_*E_];
__device__ float  g_bv[E_];
__device__ float  g_bo[E_];

// ---------------- PTX helpers ----------------
__device__ __forceinline__ uint32_t smem_u32(const void* p) {
    uint32_t a;
    asm("{ .reg .u64 t; cvta.to.shared.u64 t, %1; cvt.u32.u64 %0, t; }" : "=r"(a) : "l"(p));
    return a;
}
__device__ __forceinline__ void mma_f16(float* c, const uint32_t* a, const uint32_t* b) {
    asm volatile(
        "mma.sync.aligned.m16n8k16.row.col.f32.f16.f16.f32 "
        "{%0,%1,%2,%3}, {%4,%5,%6,%7}, {%8,%9}, {%0,%1,%2,%3};\n"
        : "+f"(c[0]), "+f"(c[1]), "+f"(c[2]), "+f"(c[3])
        : "r"(a[0]), "r"(a[1]), "r"(a[2]), "r"(a[3]), "r"(b[0]), "r"(b[1]));
}
__device__ __forceinline__ void ldsm4(uint32_t& r0, uint32_t& r1, uint32_t& r2, uint32_t& r3,
                                      uint32_t addr) {
    asm volatile("ldmatrix.sync.aligned.m8n8.x4.shared.b16 {%0,%1,%2,%3}, [%4];\n"
                 : "=r"(r0), "=r"(r1), "=r"(r2), "=r"(r3) : "r"(addr));
}
__device__ __forceinline__ void ldsm4t(uint32_t& r0, uint32_t& r1, uint32_t& r2, uint32_t& r3,
                                       uint32_t addr) {
    asm volatile("ldmatrix.sync.aligned.m8n8.x4.trans.shared.b16 {%0,%1,%2,%3}, [%4];\n"
                 : "=r"(r0), "=r"(r1), "=r"(r2), "=r"(r3) : "r"(addr));
}
__device__ __forceinline__ void cpa16(uint32_t d, const void* s) {
    asm volatile("cp.async.ca.shared.global [%0], [%1], 16;\n" :: "r"(d), "l"(s));
}
#define CP_COMMIT() asm volatile("cp.async.commit_group;\n" ::: "memory")
#define CP_WAIT(N)  asm volatile("cp.async.wait_group %0;\n" :: "n"(N) : "memory")

__device__ __forceinline__ uint32_t h2(float a, float b) {
    __half2 v = __floats2half2_rn(a, b);
    return *(uint32_t*)&v;
}
// pack (lo,hi) to f16x2 then 2^x elementwise
__device__ __forceinline__ uint32_t ex2h2(float lo, float hi) {
    uint32_t p, r;
    asm("cvt.rn.f16x2.f32 %0, %1, %2;" : "=r"(p) : "f"(hi), "f"(lo));
    asm("ex2.approx.f16x2 %0, %1;" : "=r"(r) : "r"(p));
    return r;
}
__device__ __forceinline__ uint2 f4_h4(float4 a) {
    uint2 r;
    r.x = h2(a.x, a.y);
    r.y = h2(a.z, a.w);
    return r;
}

// ---------------- prep: single merged fp32 -> fp16 conversion kernel ----------
__global__ __launch_bounds__(256) void prep_all(
        const float* __restrict__ q, const float* __restrict__ k, const float* __restrict__ v,
        const float* __restrict__ Wq, const float* __restrict__ Wk,
        const float* __restrict__ Wv_sh, const float* __restrict__ Wv_sp,
        const float* __restrict__ Wo_sh, const float* __restrict__ Wo_sp,
        const float* __restrict__ bv_sh, const float* __restrict__ bv_sp,
        const float* __restrict__ bo_sh, const float* __restrict__ bo_sp,
        const int* __restrict__ langp) {
    int bid = blockIdx.x;
    if (bid < 4096) {
        int t = bid * 256 + threadIdx.x;
        int j = t * 2;
        uint4 o;
        uint2 a, b;
        a = f4_h4(((const float4*)q)[j]); b = f4_h4(((const float4*)q)[j+1]);
        o.x = a.x; o.y = a.y; o.z = b.x; o.w = b.y;
        ((uint4*)g_qh)[t] = o;
        a = f4_h4(((const float4*)k)[j]); b = f4_h4(((const float4*)k)[j+1]);
        o.x = a.x; o.y = a.y; o.z = b.x; o.w = b.y;
        ((uint4*)g_kh)[t] = o;
        a = f4_h4(((const float4*)v)[j]); b = f4_h4(((const float4*)v)[j+1]);
        o.x = a.x; o.y = a.y; o.z = b.x; o.w = b.y;
        ((uint4*)g_vh)[t] = o;
    } else {
        int lang = langp[0];
        int i = (bid - 4096) * 256 + threadIdx.x;
        ((uint2*)g_Wqh)[i] = f4_h4(((const float4*)Wq)[i]);
        ((uint2*)g_Wkh)[i] = f4_h4(((const float4*)Wk)[i]);
        size_t so = (size_t)lang * (E_*E_/4);
        float4 s, p;
        s = ((const float4*)Wv_sh)[i];  p = ((const float4*)Wv_sp)[so + i];
        ((uint2*)g_Wvh)[i] = f4_h4(make_float4(s.x*p.x, s.y*p.y, s.z*p.z, s.w*p.w));
        s = ((const float4*)Wo_sh)[i];  p = ((const float4*)Wo_sp)[so + i];
        ((uint2*)g_Woh)[i] = f4_h4(make_float4(s.x*p.x, s.y*p.y, s.z*p.z, s.w*p.w));
        if (i < E_) {
            g_bv[i] = bv_sh[i] + bv_sp[lang*E_ + i];
            g_bo[i] = bo_sh[i] + bo_sp[lang*E_ + i];
        }
    }
}

// ---------------- fp16 GEMM core (3-stage, depth-2 prefetch — round-8 proven) -
#define BM 128
#define BN 128
#define BKH 64
#define NIT (E_/BKH)          // 8
#define TILE_U4 (BM*8)
#define NSTAGE 3

template<int HALF_OUT>
__device__ __forceinline__ void gemm_core(const __half* __restrict__ A,
                                          const __half* __restrict__ W,
                                          const float* __restrict__ bias,
                                          void* __restrict__ Cv,
                                          int bm, int bn, float cs) {
    extern __shared__ uint4 dsm[];
    uint4* sA = dsm;                       // [NSTAGE][TILE_U4]
    uint4* sB = dsm + NSTAGE*TILE_U4;      // [NSTAGE][TILE_U4]
    const int tid  = threadIdx.x;
    const int wid  = tid >> 5;
    const int lane = tid & 31;
    const int wm   = (wid >> 1) * 32;
    const int wn   = (wid & 1) * 64;
    const int grp  = lane >> 2;
    const int t4   = lane & 3;
    const uint32_t sAb = smem_u32(sA);
    const uint32_t sBb = smem_u32(sB);

    float acc[2][8][4];
    #pragma unroll
    for (int i = 0; i < 2; i++)
        #pragma unroll
        for (int j = 0; j < 8; j++)
            #pragma unroll
            for (int q = 0; q < 4; q++) acc[i][j][q] = 0.f;

    auto load_tile = [&](int it, int buf) {
        #pragma unroll
        for (int v = 0; v < 4; ++v) {
            int c = tid*4 + v;
            int r = c >> 3, ch = c & 7;
            uint32_t off = (uint32_t)(buf*TILE_U4 + r*8 + (ch ^ (r & 7))) * 16u;
            cpa16(sAb + off, (const uint4*)(A + (size_t)(bm + r)*E_ + it*BKH) + ch);
            cpa16(sBb + off, (const uint4*)(W + (size_t)(bn + r)*E_ + it*BKH) + ch);
        }
    };

    load_tile(0, 0); CP_COMMIT();
    load_tile(1, 1); CP_COMMIT();

    for (int it = 0; it < NIT; ++it) {
        if (it + 2 < NIT) {
            load_tile(it + 2, (it + 2) % NSTAGE);
            CP_COMMIT();
            CP_WAIT(2);
        } else if (it + 1 < NIT) {
            CP_WAIT(1);
        } else {
            CP_WAIT(0);
        }
        __syncthreads();

        const uint32_t aoff = (uint32_t)((it % NSTAGE)*TILE_U4) * 16u;
        #pragma unroll
        for (int k16 = 0; k16 < 4; ++k16) {
            uint32_t af[2][4];
            #pragma unroll
            for (int mf = 0; mf < 2; ++mf) {
                int row = wm + mf*16 + (lane & 15);
                int ch  = k16*2 + (lane >> 4);
                ldsm4(af[mf][0], af[mf][1], af[mf][2], af[mf][3],
                      sAb + aoff + (uint32_t)(row*8 + (ch ^ (row & 7))) * 16u);
            }
            uint32_t bf[8][2];
            #pragma unroll
            for (int np = 0; np < 4; ++np) {
                int row = wn + np*16 + (lane & 7) + ((lane >> 4) & 1)*8;
                int ch  = k16*2 + ((lane >> 3) & 1);
                ldsm4(bf[2*np][0], bf[2*np][1], bf[2*np+1][0], bf[2*np+1][1],
                      sBb + aoff + (uint32_t)(row*8 + (ch ^ (row & 7))) * 16u);
            }
            #pragma unroll
            for (int mf = 0; mf < 2; ++mf)
                #pragma unroll
                for (int nf = 0; nf < 8; ++nf)
                    mma_f16(acc[mf][nf], af[mf], bf[nf]);
        }
        __syncthreads();
    }

    #pragma unroll
    for (int mf = 0; mf < 2; ++mf) {
        #pragma unroll
        for (int nf = 0; nf < 8; ++nf) {
            int r0 = bm + wm + mf*16 + grp;
            int c0 = bn + wn + nf*8 + t4*2;
            float b0 = bias[c0], b1 = bias[c0 + 1];
            if (HALF_OUT) {
                __half* C = (__half*)Cv;
                *(uint32_t*)(C + (size_t)r0*E_ + c0)     = h2((acc[mf][nf][0] + b0)*cs, (acc[mf][nf][1] + b1)*cs);
                *(uint32_t*)(C + (size_t)(r0+8)*E_ + c0) = h2((acc[mf][nf][2] + b0)*cs, (acc[mf][nf][3] + b1)*cs);
            } else {
                float* C = (float*)Cv;
                float2 v0, v1;
                v0.x = acc[mf][nf][0] + b0; v0.y = acc[mf][nf][1] + b1;
                v1.x = acc[mf][nf][2] + b0; v1.y = acc[mf][nf][3] + b1;
                *(float2*)(C + (size_t)r0*E_ + c0)     = v0;
                *(float2*)(C + (size_t)(r0+8)*E_ + c0) = v1;
            }
        }
    }
}

#define GEMM_SMEM (2*NSTAGE*TILE_U4*16)   // 96 KB

__global__ __launch_bounds__(256) void gemm_qkv(const __half* Aq, const __half* Ak, const __half* Av,
                                                const __half* Wq, const __half* Wk, const __half* Wv,
                                                const float* bq, const float* bk, const float* bv,
                                                __half* Cq, __half* Ck, __half* Cvp) {
    const int z = blockIdx.z;
    const __half* A = (z == 0) ? Aq : (z == 1) ? Ak : Av;
    const __half* W = (z == 0) ? Wq : (z == 1) ? Wk : Wv;
    const float*  bb = (z == 0) ? bq : (z == 1) ? bk : bv;
    __half*       C = (z == 0) ? Cq : (z == 1) ? Ck : Cvp;
    float cs = (z == 0) ? 0.015625f * 1.44269504088896f : 1.f;
    gemm_core<1>(A, W, bb, C, blockIdx.y * BM, blockIdx.x * BN, cs);
}

__global__ __launch_bounds__(256) void gemm_out(const __half* __restrict__ A,
                                                const __half* __restrict__ W,
                                                const float* __restrict__ bias,
                                                float* __restrict__ C) {
    gemm_core<0>(A, W, bias, C, blockIdx.y * BM, blockIdx.x * BN, 1.f);
}

// ---------------- fp16 flash attention: 32 q-rows/warp (smem-traffic halved) ---
// Warp owns 32 query rows (256/CTA). Q in registers, so per-warp smem reads are
// UNCHANGED while output doubles -> smem crossbar (the measured binding
// resource) per q-row halves. ~200 regs -> 1 CTA/SM, 8 warps.
// 4-stage ring, write-ahead 2, single sync/iter (all warps bounded by the
// per-iteration barrier; buffer reuse distance 2).
#define KVB_U4 (64*8)                 // one K or V buffer (8 KB)
#define ANS 4
#define ATT_SMEM (2*ANS*KVB_U4*16 + ANS*64*4)   // 64 KB + 1 KB
#define NT (S_/64)

__global__ __launch_bounds__(256, 1) void attn_h(const __half* __restrict__ Q,
                                                 const __half* __restrict__ K,
                                                 const __half* __restrict__ V,
                                                 const int* __restrict__ mask,
                                                 __half* __restrict__ ctx) {
    extern __shared__ uint4 dsm[];
    uint4* sK = dsm;                       // [ANS][KVB_U4]
    uint4* sV = dsm + ANS*KVB_U4;          // [ANS][KVB_U4]
    float* mflag = (float*)(dsm + 2*ANS*KVB_U4);  // [ANS][64]

    const int bh = blockIdx.x;
    const int b  = bh >> 3;
    const int h  = bh & 7;
    const int q0 = blockIdx.y * 256;
    const int tid  = threadIdx.x;
    const int wid  = tid >> 5;
    const int lane = tid & 31;
    const int grp  = lane >> 2;
    const int t4   = lane & 3;
    const int row0 = wid * 32;
    const uint32_t sKb = smem_u32(sK);
    const uint32_t sVb = smem_u32(sV);

    const size_t kvbase = (size_t)b*S_*E_ + (size_t)h*D_;

    auto load_kv = [&](int kt, int buf) {
        const int key0 = kt * 64;
        #pragma unroll
        for (int v = 0; v < 2; ++v) {
            int c = tid*2 + v;
            int r = c >> 3, ch = c & 7;
            uint32_t off = (uint32_t)(buf*KVB_U4 + r*8 + (ch ^ (r & 7))) * 16u;
            cpa16(sKb + off, (const uint4*)(K + kvbase + (size_t)(key0 + r)*E_) + ch);
            cpa16(sVb + off, (const uint4*)(V + kvbase + (size_t)(key0 + r)*E_) + ch);
        }
    };

    // Q fragments in registers (A-operand layout), 32 rows per warp
    uint32_t qf[2][4][4];
    const __half* qb = Q + ((size_t)b*S_ + q0 + row0)*E_ + h*D_;
    #pragma unroll
    for (int mf = 0; mf < 2; ++mf) {
        #pragma unroll
        for (int k16 = 0; k16 < 4; ++k16) {
            qf[mf][k16][0] = *(const uint32_t*)(qb + (size_t)(mf*16 + grp)*E_     + k16*16 + 2*t4);
            qf[mf][k16][1] = *(const uint32_t*)(qb + (size_t)(mf*16 + grp + 8)*E_ + k16*16 + 2*t4);
            qf[mf][k16][2] = *(const uint32_t*)(qb + (size_t)(mf*16 + grp)*E_     + k16*16 + 2*t4 + 8);
            qf[mf][k16][3] = *(const uint32_t*)(qb + (size_t)(mf*16 + grp + 8)*E_ + k16*16 + 2*t4 + 8);
        }
    }

    float oacc[2][8][4];
    #pragma unroll
    for (int mf = 0; mf < 2; mf++)
        #pragma unroll
        for (int nf = 0; nf < 8; nf++)
            #pragma unroll
            for (int c = 0; c < 4; c++) oacc[mf][nf][c] = 0.f;
    float dacc[2][4] = {{0.f,0.f,0.f,0.f},{0.f,0.f,0.f,0.f}};
    const uint32_t ones2[2] = {0x3C003C00u, 0x3C003C00u};

    load_kv(0, 0); CP_COMMIT();
    load_kv(1, 1); CP_COMMIT();
    int m_cur = (tid < 64) ? mask[b*S_ + tid] : 0;
    int m_nxt = (tid < 64) ? mask[b*S_ + 64 + tid] : 0;

    for (int kt = 0; kt < NT; ++kt) {
        if (kt + 2 < NT) { load_kv(kt + 2, (kt + 2) % ANS); CP_COMMIT(); }
        if (tid < 64) mflag[(kt % ANS)*64 + tid] = m_cur ? 0.f : -60000.f;
        m_cur = m_nxt;
        if (kt + 2 < NT && tid < 64) m_nxt = mask[b*S_ + (kt + 2)*64 + tid];
        if (kt + 2 < NT)      { CP_WAIT(2); }
        else if (kt + 1 < NT) { CP_WAIT(1); }
        else                  { CP_WAIT(0); }
        __syncthreads();

        const uint32_t koff = (uint32_t)((kt % ANS)*KVB_U4) * 16u;
        const float* mf_ = mflag + (kt % ANS)*64;

        // S = Q K^T + maskoff (both 16-row halves)
        float sacc[2][8][4];
        #pragma unroll
        for (int nf = 0; nf < 8; nf++) {
            float2 mo = *(const float2*)&mf_[nf*8 + 2*t4];
            #pragma unroll
            for (int mf = 0; mf < 2; mf++) {
                sacc[mf][nf][0] = mo.x; sacc[mf][nf][1] = mo.y;
                sacc[mf][nf][2] = mo.x; sacc[mf][nf][3] = mo.y;
            }
        }
        #pragma unroll
        for (int k16 = 0; k16 < 4; ++k16) {
            #pragma unroll
            for (int np = 0; np < 4; ++np) {
                uint32_t b0, b1, b2, b3;
                int row = np*16 + (lane & 7) + ((lane >> 4) & 1)*8;
                int ch  = k16*2 + ((lane >> 3) & 1);
                ldsm4(b0, b1, b2, b3, sKb + koff + (uint32_t)(row*8 + (ch ^ (row & 7))) * 16u);
                uint32_t bb0[2] = {b0, b1}, bb1[2] = {b2, b3};
                #pragma unroll
                for (int mf = 0; mf < 2; mf++) {
                    mma_f16(sacc[mf][2*np],   qf[mf][k16], bb0);
                    mma_f16(sacc[mf][2*np+1], qf[mf][k16], bb1);
                }
            }
        }

        // p = 2^s -> PV A-fragments
        uint32_t pf[2][4][4];
        #pragma unroll
        for (int mf = 0; mf < 2; mf++)
            #pragma unroll
            for (int nf = 0; nf < 8; nf++) {
                pf[mf][nf >> 1][(nf & 1) * 2]     = ex2h2(sacc[mf][nf][0], sacc[mf][nf][1]);
                pf[mf][nf >> 1][(nf & 1) * 2 + 1] = ex2h2(sacc[mf][nf][2], sacc[mf][nf][3]);
            }

        // O += P V ; denominator += P * ones
        #pragma unroll
        for (int k16 = 0; k16 < 4; ++k16) {
            #pragma unroll
            for (int np = 0; np < 4; ++np) {
                uint32_t b0, b1, b2, b3;
                int row = k16*16 + (lane & 7) + ((lane >> 3) & 1)*8;
                int ch  = np*2 + ((lane >> 4) & 1);
                ldsm4t(b0, b1, b2, b3, sVb + koff + (uint32_t)(row*8 + (ch ^ (row & 7))) * 16u);
                uint32_t bb0[2] = {b0, b1}, bb1[2] = {b2, b3};
                #pragma unroll
                for (int mf = 0; mf < 2; mf++) {
                    mma_f16(oacc[mf][2*np],   pf[mf][k16], bb0);
                    mma_f16(oacc[mf][2*np+1], pf[mf][k16], bb1);
                }
            }
            #pragma unroll
            for (int mf = 0; mf < 2; mf++)
                mma_f16(dacc[mf], pf[mf][k16], ones2);
        }
        // no trailing sync: buffer reuse distance 2 (ANS=4, write-ahead 2)
    }

    #pragma unroll
    for (int mf = 0; mf < 2; mf++) {
        float i0 = 1.f / dacc[mf][0], i1 = 1.f / dacc[mf][2];
        __half* op = ctx + ((size_t)b*S_ + q0 + row0 + mf*16)*E_ + h*D_;
        #pragma unroll
        for (int nf = 0; nf < 8; nf++) {
            int c0 = nf*8 + 2*t4;
            *(uint32_t*)(op + (size_t)grp*E_ + c0)     = h2(oacc[mf][nf][0]*i0, oacc[mf][nf][1]*i0);
            *(uint32_t*)(op + (size_t)(grp+8)*E_ + c0) = h2(oacc[mf][nf][2]*i1, oacc[mf][nf][3]*i1);
        }
    }
}

// ---------------- launch ----------------
extern "C" void kernel_launch(void* const* d_in, const int* in_sizes, int n_in,
                              void* d_out, int out_size) {
    const float* q      = (const float*)d_in[0];
    const float* k      = (const float*)d_in[1];
    const float* v      = (const float*)d_in[2];
    const float* Wq     = (const float*)d_in[3];
    const float* bq     = (const float*)d_in[4];
    const float* Wk     = (const float*)d_in[5];
    const float* bk     = (const float*)d_in[6];
    const float* Wv_sh  = (const float*)d_in[7];
    const float* Wv_sp  = (const float*)d_in[8];
    const float* bv_sh  = (const float*)d_in[9];
    const float* bv_sp  = (const float*)d_in[10];
    const float* Wo_sh  = (const float*)d_in[11];
    const float* Wo_sp  = (const float*)d_in[12];
    const float* bo_sh  = (const float*)d_in[13];
    const float* bo_sp  = (const float*)d_in[14];
    const int*   mask   = (const int*)d_in[15];
    const int*   lang   = (const int*)d_in[16];

    void *pqh, *pkh, *pvh, *pQh, *pKh, *pVh, *pctx;
    void *pWq, *pWk, *pWv, *pWo, *pbv, *pbo;
    cudaGetSymbolAddress(&pqh, g_qh);
    cudaGetSymbolAddress(&pkh, g_kh);
    cudaGetSymbolAddress(&pvh, g_vh);
    cudaGetSymbolAddress(&pQh, g_Qh);
    cudaGetSymbolAddress(&pKh, g_Kh);
    cudaGetSymbolAddress(&pVh, g_Vh);
    cudaGetSymbolAddress(&pctx, g_ctxh);
    cudaGetSymbolAddress(&pWq, g_Wqh);
    cudaGetSymbolAddress(&pWk, g_Wkh);
    cudaGetSymbolAddress(&pWv, g_Wvh);
    cudaGetSymbolAddress(&pWo, g_Woh);
    cudaGetSymbolAddress(&pbv, g_bv);
    cudaGetSymbolAddress(&pbo, g_bo);

    static int attr_set = 0;
    if (!attr_set) {
        cudaFuncSetAttribute(gemm_qkv, cudaFuncAttributeMaxDynamicSharedMemorySize, GEMM_SMEM);
        cudaFuncSetAttribute(gemm_out, cudaFuncAttributeMaxDynamicSharedMemorySize, GEMM_SMEM);
        cudaFuncSetAttribute(attn_h,   cudaFuncAttributeMaxDynamicSharedMemorySize, ATT_SMEM);
        attr_set = 1;
    }

    prep_all<<<4096 + 256, 256>>>(q, k, v, Wq, Wk, Wv_sh, Wv_sp, Wo_sh, Wo_sp,
                                  bv_sh, bv_sp, bo_sh, bo_sp, lang);

    dim3 gq(E_/BN, M_/BM, 3);   // (4, 128, 3)
    gemm_qkv<<<gq, 256, GEMM_SMEM>>>((const __half*)pqh, (const __half*)pkh, (const __half*)pvh,
                                     (const __half*)pWq, (const __half*)pWk, (const __half*)pWv,
                                     bq, bk, (const float*)pbv,
                                     (__half*)pQh, (__half*)pKh, (__half*)pVh);

    attn_h<<<dim3(B_*H_, S_/256), 256, ATT_SMEM>>>((const __half*)pQh, (const __half*)pKh,
                                                   (const __half*)pVh, mask, (__half*)pctx);

    dim3 gg(E_/BN, M_/BM);   // (4, 128)
    gemm_out<<<gg, 256, GEMM_SMEM>>>((const __half*)pctx, (const __half*)pWo,
                                     (const float*)pbo, (float*)d_out);
}

// round 11
// speedup vs baseline: 1.6630x; 1.1410x over previous
#include <cuda_runtime.h>
#include <cuda_fp16.h>
#include <cstdint>

#define B_ 16
#define S_ 1024
#define E_ 512
#define H_ 8
#define D_ 64
#define L_ 4
#define M_ (B_*S_)   // 16384 rows

// ---------------- device scratch (no allocations allowed) ----------------
__device__ __half g_qh[M_*E_];
__device__ __half g_kh[M_*E_];
__device__ __half g_vh[M_*E_];
__device__ __half g_Qh[M_*E_];
__device__ __half g_Kh[M_*E_];
__device__ __half g_Vh[M_*E_];
__device__ __half g_ctxh[M_*E_];
__device__ __half g_Wqh[E_*E_];
__device__ __half g_Wkh[E_*E_];
__device__ __half g_Wvh[E_*E_];
__device__ __half g_Woh[E_*E_];
__device__ float  g_bv[E_];
__device__ float  g_bo[E_];

// ---------------- PTX helpers ----------------
__device__ __forceinline__ uint32_t smem_u32(const void* p) {
    uint32_t a;
    asm("{ .reg .u64 t; cvta.to.shared.u64 t, %1; cvt.u32.u64 %0, t; }" : "=r"(a) : "l"(p));
    return a;
}
__device__ __forceinline__ void mma_f16(float* c, const uint32_t* a, const uint32_t* b) {
    asm volatile(
        "mma.sync.aligned.m16n8k16.row.col.f32.f16.f16.f32 "
        "{%0,%1,%2,%3}, {%4,%5,%6,%7}, {%8,%9}, {%0,%1,%2,%3};\n"
        : "+f"(c[0]), "+f"(c[1]), "+f"(c[2]), "+f"(c[3])
        : "r"(a[0]), "r"(a[1]), "r"(a[2]), "r"(a[3]), "r"(b[0]), "r"(b[1]));
}
__device__ __forceinline__ void ldsm4(uint32_t& r0, uint32_t& r1, uint32_t& r2, uint32_t& r3,
                                      uint32_t addr) {
    asm volatile("ldmatrix.sync.aligned.m8n8.x4.shared.b16 {%0,%1,%2,%3}, [%4];\n"
                 : "=r"(r0), "=r"(r1), "=r"(r2), "=r"(r3) : "r"(addr));
}
__device__ __forceinline__ void ldsm4t(uint32_t& r0, uint32_t& r1, uint32_t& r2, uint32_t& r3,
                                       uint32_t addr) {
    asm volatile("ldmatrix.sync.aligned.m8n8.x4.trans.shared.b16 {%0,%1,%2,%3}, [%4];\n"
                 : "=r"(r0), "=r"(r1), "=r"(r2), "=r"(r3) : "r"(addr));
}
__device__ __forceinline__ void cpa16(uint32_t d, const void* s) {
    asm volatile("cp.async.ca.shared.global [%0], [%1], 16;\n" :: "r"(d), "l"(s));
}
#define CP_COMMIT() asm volatile("cp.async.commit_group;\n" ::: "memory")
#define CP_WAIT(N)  asm volatile("cp.async.wait_group %0;\n" :: "n"(N) : "memory")

__device__ __forceinline__ uint32_t h2(float a, float b) {
    __half2 v = __floats2half2_rn(a, b);
    return *(uint32_t*)&v;
}
// pack (lo,hi) to f16x2 then 2^x elementwise
__device__ __forceinline__ uint32_t ex2h2(float lo, float hi) {
    uint32_t p, r;
    asm("cvt.rn.f16x2.f32 %0, %1, %2;" : "=r"(p) : "f"(hi), "f"(lo));
    asm("ex2.approx.f16x2 %0, %1;" : "=r"(r) : "r"(p));
    return r;
}
__device__ __forceinline__ uint2 f4_h4(float4 a) {
    uint2 r;
    r.x = h2(a.x, a.y);
    r.y = h2(a.z, a.w);
    return r;
}

// ---------------- prep: single merged fp32 -> fp16 conversion kernel ----------
__global__ __launch_bounds__(256) void prep_all(
        const float* __restrict__ q, const float* __restrict__ k, const float* __restrict__ v,
        const float* __restrict__ Wq, const float* __restrict__ Wk,
        const float* __restrict__ Wv_sh, const float* __restrict__ Wv_sp,
        const float* __restrict__ Wo_sh, const float* __restrict__ Wo_sp,
        const float* __restrict__ bv_sh, const float* __restrict__ bv_sp,
        const float* __restrict__ bo_sh, const float* __restrict__ bo_sp,
        const int* __restrict__ langp) {
    int bid = blockIdx.x;
    if (bid < 4096) {
        int t = bid * 256 + threadIdx.x;
        int j = t * 2;
        uint4 o;
        uint2 a, b;
        a = f4_h4(((const float4*)q)[j]); b = f4_h4(((const float4*)q)[j+1]);
        o.x = a.x; o.y = a.y; o.z = b.x; o.w = b.y;
        ((uint4*)g_qh)[t] = o;
        a = f4_h4(((const float4*)k)[j]); b = f4_h4(((const float4*)k)[j+1]);
        o.x = a.x; o.y = a.y; o.z = b.x; o.w = b.y;
        ((uint4*)g_kh)[t] = o;
        a = f4_h4(((const float4*)v)[j]); b = f4_h4(((const float4*)v)[j+1]);
        o.x = a.x; o.y = a.y; o.z = b.x; o.w = b.y;
        ((uint4*)g_vh)[t] = o;
    } else {
        int lang = langp[0];
        int i = (bid - 4096) * 256 + threadIdx.x;
        ((uint2*)g_Wqh)[i] = f4_h4(((const float4*)Wq)[i]);
        ((uint2*)g_Wkh)[i] = f4_h4(((const float4*)Wk)[i]);
        size_t so = (size_t)lang * (E_*E_/4);
        float4 s, p;
        s = ((const float4*)Wv_sh)[i];  p = ((const float4*)Wv_sp)[so + i];
        ((uint2*)g_Wvh)[i] = f4_h4(make_float4(s.x*p.x, s.y*p.y, s.z*p.z, s.w*p.w));
        s = ((const float4*)Wo_sh)[i];  p = ((const float4*)Wo_sp)[so + i];
        ((uint2*)g_Woh)[i] = f4_h4(make_float4(s.x*p.x, s.y*p.y, s.z*p.z, s.w*p.w));
        if (i < E_) {
            g_bv[i] = bv_sh[i] + bv_sp[lang*E_ + i];
            g_bo[i] = bo_sh[i] + bo_sp[lang*E_ + i];
        }
    }
}

// ---------------- fp16 GEMM: 256x128 CTA tile, 64x64 warp tile, BKH=128 -------
// 8 warps (4Mx2N), NSTAGE=2 (96 KB/stage, 192 KB -> 1 CTA/SM).
// 256 MMAs per warp between barrier pairs (4x previous), NIT=4.
// Rows are 256B = 16 uint4 chunks; swizzle per 128B half-row:
//   swz(ch, r) = (ch & 8) | ((ch ^ r) & 7)
#define BM 256
#define BN 128
#define BKH 128
#define NIT (E_/BKH)          // 4
#define A_U4 (BM*16)          // 4096 uint4
#define B_U4 (BN*16)          // 2048 uint4
#define STAGE_U4 (A_U4 + B_U4)
#define GEMM_SMEM (2*STAGE_U4*16)   // 192 KB

__device__ __forceinline__ int gswz(int ch, int r) {
    return (ch & 8) | ((ch ^ r) & 7);
}

template<int HALF_OUT>
__device__ __forceinline__ void gemm_core(const __half* __restrict__ A,
                                          const __half* __restrict__ W,
                                          const float* __restrict__ bias,
                                          void* __restrict__ Cv,
                                          int bm, int bn, float cs) {
    extern __shared__ uint4 dsm[];
    const int tid  = threadIdx.x;
    const int wid  = tid >> 5;
    const int lane = tid & 31;
    const int wm   = (wid >> 1) * 64;    // 4 M-groups of 64
    const int wn   = (wid & 1) * 64;     // 2 N-groups of 64
    const int grp  = lane >> 2;
    const int t4   = lane & 3;
    const uint32_t sb = smem_u32(dsm);

    float acc[4][8][4];
    #pragma unroll
    for (int i = 0; i < 4; i++)
        #pragma unroll
        for (int j = 0; j < 8; j++)
            #pragma unroll
            for (int q = 0; q < 4; q++) acc[i][j][q] = 0.f;

    auto load_tile = [&](int it, int buf) {
        uint32_t abase = sb + (uint32_t)(buf*STAGE_U4) * 16u;
        uint32_t bbase = abase + (uint32_t)A_U4 * 16u;
        #pragma unroll
        for (int v = 0; v < 16; ++v) {           // A: 4096 chunks
            int c = v*256 + tid;
            int r = c >> 4, ch = c & 15;
            cpa16(abase + (uint32_t)(r*16 + gswz(ch, r)) * 16u,
                  (const uint4*)(A + (size_t)(bm + r)*E_ + it*BKH) + ch);
        }
        #pragma unroll
        for (int v = 0; v < 8; ++v) {            // B: 2048 chunks
            int c = v*256 + tid;
            int r = c >> 4, ch = c & 15;
            cpa16(bbase + (uint32_t)(r*16 + gswz(ch, r)) * 16u,
                  (const uint4*)(W + (size_t)(bn + r)*E_ + it*BKH) + ch);
        }
    };

    load_tile(0, 0); CP_COMMIT();

    for (int it = 0; it < NIT; ++it) {
        // leading sync: all warps done computing it-1 -> buffer (it+1)&1 is free
        __syncthreads();
        if (it + 1 < NIT) {
            load_tile(it + 1, (it + 1) & 1);
            CP_COMMIT();
            CP_WAIT(1);
        } else {
            CP_WAIT(0);
        }
        __syncthreads();   // tile `it` data visible to all warps

        const uint32_t abase = sb + (uint32_t)((it & 1)*STAGE_U4) * 16u;
        const uint32_t bbase = abase + (uint32_t)A_U4 * 16u;
        #pragma unroll
        for (int k16 = 0; k16 < 8; ++k16) {
            uint32_t af[4][4];
            #pragma unroll
            for (int mf = 0; mf < 4; ++mf) {
                int row = wm + mf*16 + (lane & 15);
                int ch  = k16*2 + (lane >> 4);
                ldsm4(af[mf][0], af[mf][1], af[mf][2], af[mf][3],
                      abase + (uint32_t)(row*16 + gswz(ch, row)) * 16u);
            }
            uint32_t bf[8][2];
            #pragma unroll
            for (int np = 0; np < 4; ++np) {
                int row = wn + np*16 + (lane & 7) + ((lane >> 4) & 1)*8;
                int ch  = k16*2 + ((lane >> 3) & 1);
                ldsm4(bf[2*np][0], bf[2*np][1], bf[2*np+1][0], bf[2*np+1][1],
                      bbase + (uint32_t)(row*16 + gswz(ch, row)) * 16u);
            }
            #pragma unroll
            for (int mf = 0; mf < 4; ++mf)
                #pragma unroll
                for (int nf = 0; nf < 8; ++nf)
                    mma_f16(acc[mf][nf], af[mf], bf[nf]);
        }
    }

    #pragma unroll
    for (int mf = 0; mf < 4; ++mf) {
        #pragma unroll
        for (int nf = 0; nf < 8; ++nf) {
            int r0 = bm + wm + mf*16 + grp;
            int c0 = bn + wn + nf*8 + t4*2;
            float b0 = bias[c0], b1 = bias[c0 + 1];
            if (HALF_OUT) {
                __half* C = (__half*)Cv;
                *(uint32_t*)(C + (size_t)r0*E_ + c0)     = h2((acc[mf][nf][0] + b0)*cs, (acc[mf][nf][1] + b1)*cs);
                *(uint32_t*)(C + (size_t)(r0+8)*E_ + c0) = h2((acc[mf][nf][2] + b0)*cs, (acc[mf][nf][3] + b1)*cs);
            } else {
                float* C = (float*)Cv;
                float2 v0, v1;
                v0.x = acc[mf][nf][0] + b0; v0.y = acc[mf][nf][1] + b1;
                v1.x = acc[mf][nf][2] + b0; v1.y = acc[mf][nf][3] + b1;
                *(float2*)(C + (size_t)r0*E_ + c0)     = v0;
                *(float2*)(C + (size_t)(r0+8)*E_ + c0) = v1;
            }
        }
    }
}

__global__ __launch_bounds__(256, 1) void gemm_qkv(const __half* Aq, const __half* Ak, const __half* Av,
                                                   const __half* Wq, const __half* Wk, const __half* Wv,
                                                   const float* bq, const float* bk, const float* bv,
                                                   __half* Cq, __half* Ck, __half* Cvp) {
    const int z = blockIdx.z;
    const __half* A = (z == 0) ? Aq : (z == 1) ? Ak : Av;
    const __half* W = (z == 0) ? Wq : (z == 1) ? Wk : Wv;
    const float*  bb = (z == 0) ? bq : (z == 1) ? bk : bv;
    __half*       C = (z == 0) ? Cq : (z == 1) ? Ck : Cvp;
    float cs = (z == 0) ? 0.015625f * 1.44269504088896f : 1.f;
    gemm_core<1>(A, W, bb, C, blockIdx.y * BM, blockIdx.x * BN, cs);
}

__global__ __launch_bounds__(256, 1) void gemm_out(const __half* __restrict__ A,
                                                   const __half* __restrict__ W,
                                                   const float* __restrict__ bias,
                                                   float* __restrict__ C) {
    gemm_core<0>(A, W, bias, C, blockIdx.y * BM, blockIdx.x * BN, 1.f);
}

// ---------------- fp16 flash attention: 32 q-rows/warp (round-10 proven) ------
#define KVB_U4 (64*8)
#define ANS 4
#define ATT_SMEM (2*ANS*KVB_U4*16 + ANS*64*4)
#define NT (S_/64)

__global__ __launch_bounds__(256, 1) void attn_h(const __half* __restrict__ Q,
                                                 const __half* __restrict__ K,
                                                 const __half* __restrict__ V,
                                                 const int* __restrict__ mask,
                                                 __half* __restrict__ ctx) {
    extern __shared__ uint4 dsm[];
    uint4* sK = dsm;
    uint4* sV = dsm + ANS*KVB_U4;
    float* mflag = (float*)(dsm + 2*ANS*KVB_U4);

    const int bh = blockIdx.x;
    const int b  = bh >> 3;
    const int h  = bh & 7;
    const int q0 = blockIdx.y * 256;
    const int tid  = threadIdx.x;
    const int wid  = tid >> 5;
    const int lane = tid & 31;
    const int grp  = lane >> 2;
    const int t4   = lane & 3;
    const int row0 = wid * 32;
    const uint32_t sKb = smem_u32(sK);
    const uint32_t sVb = smem_u32(sV);

    const size_t kvbase = (size_t)b*S_*E_ + (size_t)h*D_;

    auto load_kv = [&](int kt, int buf) {
        const int key0 = kt * 64;
        #pragma unroll
        for (int v = 0; v < 2; ++v) {
            int c = tid*2 + v;
            int r = c >> 3, ch = c & 7;
            uint32_t off = (uint32_t)(buf*KVB_U4 + r*8 + (ch ^ (r & 7))) * 16u;
            cpa16(sKb + off, (const uint4*)(K + kvbase + (size_t)(key0 + r)*E_) + ch);
            cpa16(sVb + off, (const uint4*)(V + kvbase + (size_t)(key0 + r)*E_) + ch);
        }
    };

    uint32_t qf[2][4][4];
    const __half* qb = Q + ((size_t)b*S_ + q0 + row0)*E_ + h*D_;
    #pragma unroll
    for (int mf = 0; mf < 2; ++mf) {
        #pragma unroll
        for (int k16 = 0; k16 < 4; ++k16) {
            qf[mf][k16][0] = *(const uint32_t*)(qb + (size_t)(mf*16 + grp)*E_     + k16*16 + 2*t4);
            qf[mf][k16][1] = *(const uint32_t*)(qb + (size_t)(mf*16 + grp + 8)*E_ + k16*16 + 2*t4);
            qf[mf][k16][2] = *(const uint32_t*)(qb + (size_t)(mf*16 + grp)*E_     + k16*16 + 2*t4 + 8);
            qf[mf][k16][3] = *(const uint32_t*)(qb + (size_t)(mf*16 + grp + 8)*E_ + k16*16 + 2*t4 + 8);
        }
    }

    float oacc[2][8][4];
    #pragma unroll
    for (int mf = 0; mf < 2; mf++)
        #pragma unroll
        for (int nf = 0; nf < 8; nf++)
            #pragma unroll
            for (int c = 0; c < 4; c++) oacc[mf][nf][c] = 0.f;
    float dacc[2][4] = {{0.f,0.f,0.f,0.f},{0.f,0.f,0.f,0.f}};
    const uint32_t ones2[2] = {0x3C003C00u, 0x3C003C00u};

    load_kv(0, 0); CP_COMMIT();
    load_kv(1, 1); CP_COMMIT();
    int m_cur = (tid < 64) ? mask[b*S_ + tid] : 0;
    int m_nxt = (tid < 64) ? mask[b*S_ + 64 + tid] : 0;

    for (int kt = 0; kt < NT; ++kt) {
        if (kt + 2 < NT) { load_kv(kt + 2, (kt + 2) % ANS); CP_COMMIT(); }
        if (tid < 64) mflag[(kt % ANS)*64 + tid] = m_cur ? 0.f : -60000.f;
        m_cur = m_nxt;
        if (kt + 2 < NT && tid < 64) m_nxt = mask[b*S_ + (kt + 2)*64 + tid];
        if (kt + 2 < NT)      { CP_WAIT(2); }
        else if (kt + 1 < NT) { CP_WAIT(1); }
        else                  { CP_WAIT(0); }
        __syncthreads();

        const uint32_t koff = (uint32_t)((kt % ANS)*KVB_U4) * 16u;
        const float* mf_ = mflag + (kt % ANS)*64;

        float sacc[2][8][4];
        #pragma unroll
        for (int nf = 0; nf < 8; nf++) {
            float2 mo = *(const float2*)&mf_[nf*8 + 2*t4];
            #pragma unroll
            for (int mf = 0; mf < 2; mf++) {
                sacc[mf][nf][0] = mo.x; sacc[mf][nf][1] = mo.y;
                sacc[mf][nf][2] = mo.x; sacc[mf][nf][3] = mo.y;
            }
        }
        #pragma unroll
        for (int k16 = 0; k16 < 4; ++k16) {
            #pragma unroll
            for (int np = 0; np < 4; ++np) {
                uint32_t b0, b1, b2, b3;
                int row = np*16 + (lane & 7) + ((lane >> 4) & 1)*8;
                int ch  = k16*2 + ((lane >> 3) & 1);
                ldsm4(b0, b1, b2, b3, sKb + koff + (uint32_t)(row*8 + (ch ^ (row & 7))) * 16u);
                uint32_t bb0[2] = {b0, b1}, bb1[2] = {b2, b3};
                #pragma unroll
                for (int mf = 0; mf < 2; mf++) {
                    mma_f16(sacc[mf][2*np],   qf[mf][k16], bb0);
                    mma_f16(sacc[mf][2*np+1], qf[mf][k16], bb1);
                }
            }
        }

        uint32_t pf[2][4][4];
        #pragma unroll
        for (int mf = 0; mf < 2; mf++)
            #pragma unroll
            for (int nf = 0; nf < 8; nf++) {
                pf[mf][nf >> 1][(nf & 1) * 2]     = ex2h2(sacc[mf][nf][0], sacc[mf][nf][1]);
                pf[mf][nf >> 1][(nf & 1) * 2 + 1] = ex2h2(sacc[mf][nf][2], sacc[mf][nf][3]);
            }

        #pragma unroll
        for (int k16 = 0; k16 < 4; ++k16) {
            #pragma unroll
            for (int np = 0; np < 4; ++np) {
                uint32_t b0, b1, b2, b3;
                int row = k16*16 + (lane & 7) + ((lane >> 3) & 1)*8;
                int ch  = np*2 + ((lane >> 4) & 1);
                ldsm4t(b0, b1, b2, b3, sVb + koff + (uint32_t)(row*8 + (ch ^ (row & 7))) * 16u);
                uint32_t bb0[2] = {b0, b1}, bb1[2] = {b2, b3};
                #pragma unroll
                for (int mf = 0; mf < 2; mf++) {
                    mma_f16(oacc[mf][2*np],   pf[mf][k16], bb0);
                    mma_f16(oacc[mf][2*np+1], pf[mf][k16], bb1);
                }
            }
            #pragma unroll
            for (int mf = 0; mf < 2; mf++)
                mma_f16(dacc[mf], pf[mf][k16], ones2);
        }
    }

    #pragma unroll
    for (int mf = 0; mf < 2; mf++) {
        float i0 = 1.f / dacc[mf][0], i1 = 1.f / dacc[mf][2];
        __half* op = ctx + ((size_t)b*S_ + q0 + row0 + mf*16)*E_ + h*D_;
        #pragma unroll
        for (int nf = 0; nf < 8; nf++) {
            int c0 = nf*8 + 2*t4;
            *(uint32_t*)(op + (size_t)grp*E_ + c0)     = h2(oacc[mf][nf][0]*i0, oacc[mf][nf][1]*i0);
            *(uint32_t*)(op + (size_t)(grp+8)*E_ + c0) = h2(oacc[mf][nf][2]*i1, oacc[mf][nf][3]*i1);
        }
    }
}

// ---------------- launch ----------------
extern "C" void kernel_launch(void* const* d_in, const int* in_sizes, int n_in,
                              void* d_out, int out_size) {
    const float* q      = (const float*)d_in[0];
    const float* k      = (const float*)d_in[1];
    const float* v      = (const float*)d_in[2];
    const float* Wq     = (const float*)d_in[3];
    const float* bq     = (const float*)d_in[4];
    const float* Wk     = (const float*)d_in[5];
    const float* bk     = (const float*)d_in[6];
    const float* Wv_sh  = (const float*)d_in[7];
    const float* Wv_sp  = (const float*)d_in[8];
    const float* bv_sh  = (const float*)d_in[9];
    const float* bv_sp  = (const float*)d_in[10];
    const float* Wo_sh  = (const float*)d_in[11];
    const float* Wo_sp  = (const float*)d_in[12];
    const float* bo_sh  = (const float*)d_in[13];
    const float* bo_sp  = (const float*)d_in[14];
    const int*   mask   = (const int*)d_in[15];
    const int*   lang   = (const int*)d_in[16];

    void *pqh, *pkh, *pvh, *pQh, *pKh, *pVh, *pctx;
    void *pWq, *pWk, *pWv, *pWo, *pbv, *pbo;
    cudaGetSymbolAddress(&pqh, g_qh);
    cudaGetSymbolAddress(&pkh, g_kh);
    cudaGetSymbolAddress(&pvh, g_vh);
    cudaGetSymbolAddress(&pQh, g_Qh);
    cudaGetSymbolAddress(&pKh, g_Kh);
    cudaGetSymbolAddress(&pVh, g_Vh);
    cudaGetSymbolAddress(&pctx, g_ctxh);
    cudaGetSymbolAddress(&pWq, g_Wqh);
    cudaGetSymbolAddress(&pWk, g_Wkh);
    cudaGetSymbolAddress(&pWv, g_Wvh);
    cudaGetSymbolAddress(&pWo, g_Woh);
    cudaGetSymbolAddress(&pbv, g_bv);
    cudaGetSymbolAddress(&pbo, g_bo);

    static int attr_set = 0;
    if (!attr_set) {
        cudaFuncSetAttribute(gemm_qkv, cudaFuncAttributeMaxDynamicSharedMemorySize, GEMM_SMEM);
        cudaFuncSetAttribute(gemm_out, cudaFuncAttributeMaxDynamicSharedMemorySize, GEMM_SMEM);
        cudaFuncSetAttribute(attn_h,   cudaFuncAttributeMaxDynamicSharedMemorySize, ATT_SMEM);
        attr_set = 1;
    }

    prep_all<<<4096 + 256, 256>>>(q, k, v, Wq, Wk, Wv_sh, Wv_sp, Wo_sh, Wo_sp,
                                  bv_sh, bv_sp, bo_sh, bo_sp, lang);

    dim3 gq(E_/BN, M_/BM, 3);   // (4, 64, 3)
    gemm_qkv<<<gq, 256, GEMM_SMEM>>>((const __half*)pqh, (const __half*)pkh, (const __half*)pvh,
                                     (const __half*)pWq, (const __half*)pWk, (const __half*)pWv,
                                     bq, bk, (const float*)pbv,
                                     (__half*)pQh, (__half*)pKh, (__half*)pVh);

    attn_h<<<dim3(B_*H_, S_/256), 256, ATT_SMEM>>>((const __half*)pQh, (const __half*)pKh,
                                                   (const __half*)pVh, mask, (__half*)pctx);

    dim3 gg(E_/BN, M_/BM);   // (4, 64)
    gemm_out<<<gg, 256, GEMM_SMEM>>>((const __half*)pctx, (const __half*)pWo,
                                     (const float*)pbo, (float*)d_out);
}

// round 14
// speedup vs baseline: 1.6665x; 1.0021x over previous
#include <cuda_runtime.h>
#include <cuda_fp16.h>
#include <cstdint>

#define B_ 16
#define S_ 1024
#define E_ 512
#define H_ 8
#define D_ 64
#define L_ 4
#define M_ (B_*S_)   // 16384 rows

// ---------------- device scratch (no allocations allowed) ----------------
__device__ __half g_qh[M_*E_];
__device__ __half g_kh[M_*E_];
__device__ __half g_vh[M_*E_];
__device__ __half g_Qh[M_*E_];
__device__ __half g_Kh[M_*E_];
__device__ __half g_Vh[M_*E_];
__device__ __half g_ctxh[M_*E_];
__device__ __half g_Wqh[E_*E_];
__device__ __half g_Wkh[E_*E_];
__device__ __half g_Wvh[E_*E_];
__device__ __half g_Woh[E_*E_];
__device__ float  g_bv[E_];
__device__ float  g_bo[E_];

// ---------------- PTX helpers ----------------
__device__ __forceinline__ uint32_t smem_u32(const void* p) {
    uint32_t a;
    asm("{ .reg .u64 t; cvta.to.shared.u64 t, %1; cvt.u32.u64 %0, t; }" : "=r"(a) : "l"(p));
    return a;
}
__device__ __forceinline__ void mma_f16(float* c, const uint32_t* a, const uint32_t* b) {
    asm volatile(
        "mma.sync.aligned.m16n8k16.row.col.f32.f16.f16.f32 "
        "{%0,%1,%2,%3}, {%4,%5,%6,%7}, {%8,%9}, {%0,%1,%2,%3};\n"
        : "+f"(c[0]), "+f"(c[1]), "+f"(c[2]), "+f"(c[3])
        : "r"(a[0]), "r"(a[1]), "r"(a[2]), "r"(a[3]), "r"(b[0]), "r"(b[1]));
}
__device__ __forceinline__ void ldsm4(uint32_t& r0, uint32_t& r1, uint32_t& r2, uint32_t& r3,
                                      uint32_t addr) {
    asm volatile("ldmatrix.sync.aligned.m8n8.x4.shared.b16 {%0,%1,%2,%3}, [%4];\n"
                 : "=r"(r0), "=r"(r1), "=r"(r2), "=r"(r3) : "r"(addr));
}
__device__ __forceinline__ void ldsm4t(uint32_t& r0, uint32_t& r1, uint32_t& r2, uint32_t& r3,
                                       uint32_t addr) {
    asm volatile("ldmatrix.sync.aligned.m8n8.x4.trans.shared.b16 {%0,%1,%2,%3}, [%4];\n"
                 : "=r"(r0), "=r"(r1), "=r"(r2), "=r"(r3) : "r"(addr));
}
__device__ __forceinline__ void cpa16(uint32_t d, const void* s) {
    asm volatile("cp.async.ca.shared.global [%0], [%1], 16;\n" :: "r"(d), "l"(s));
}
#define CP_COMMIT() asm volatile("cp.async.commit_group;\n" ::: "memory")
#define CP_WAIT(N)  asm volatile("cp.async.wait_group %0;\n" :: "n"(N) : "memory")

__device__ __forceinline__ uint32_t h2(float a, float b) {
    __half2 v = __floats2half2_rn(a, b);
    return *(uint32_t*)&v;
}
// pack (lo,hi) to f16x2 then 2^x elementwise
__device__ __forceinline__ uint32_t ex2h2(float lo, float hi) {
    uint32_t p, r;
    asm("cvt.rn.f16x2.f32 %0, %1, %2;" : "=r"(p) : "f"(hi), "f"(lo));
    asm("ex2.approx.f16x2 %0, %1;" : "=r"(r) : "r"(p));
    return r;
}
__device__ __forceinline__ uint2 f4_h4(float4 a) {
    uint2 r;
    r.x = h2(a.x, a.y);
    r.y = h2(a.z, a.w);
    return r;
}

// ---------------- prep: single merged fp32 -> fp16 conversion kernel ----------
__global__ __launch_bounds__(256) void prep_all(
        const float* __restrict__ q, const float* __restrict__ k, const float* __restrict__ v,
        const float* __restrict__ Wq, const float* __restrict__ Wk,
        const float* __restrict__ Wv_sh, const float* __restrict__ Wv_sp,
        const float* __restrict__ Wo_sh, const float* __restrict__ Wo_sp,
        const float* __restrict__ bv_sh, const float* __restrict__ bv_sp,
        const float* __restrict__ bo_sh, const float* __restrict__ bo_sp,
        const int* __restrict__ langp) {
    int bid = blockIdx.x;
    if (bid < 4096) {
        int t = bid * 256 + threadIdx.x;
        int j = t * 2;
        uint4 o;
        uint2 a, b;
        a = f4_h4(((const float4*)q)[j]); b = f4_h4(((const float4*)q)[j+1]);
        o.x = a.x; o.y = a.y; o.z = b.x; o.w = b.y;
        ((uint4*)g_qh)[t] = o;
        a = f4_h4(((const float4*)k)[j]); b = f4_h4(((const float4*)k)[j+1]);
        o.x = a.x; o.y = a.y; o.z = b.x; o.w = b.y;
        ((uint4*)g_kh)[t] = o;
        a = f4_h4(((const float4*)v)[j]); b = f4_h4(((const float4*)v)[j+1]);
        o.x = a.x; o.y = a.y; o.z = b.x; o.w = b.y;
        ((uint4*)g_vh)[t] = o;
    } else {
        int lang = langp[0];
        int i = (bid - 4096) * 256 + threadIdx.x;
        ((uint2*)g_Wqh)[i] = f4_h4(((const float4*)Wq)[i]);
        ((uint2*)g_Wkh)[i] = f4_h4(((const float4*)Wk)[i]);
        size_t so = (size_t)lang * (E_*E_/4);
        float4 s, p;
        s = ((const float4*)Wv_sh)[i];  p = ((const float4*)Wv_sp)[so + i];
        ((uint2*)g_Wvh)[i] = f4_h4(make_float4(s.x*p.x, s.y*p.y, s.z*p.z, s.w*p.w));
        s = ((const float4*)Wo_sh)[i];  p = ((const float4*)Wo_sp)[so + i];
        ((uint2*)g_Woh)[i] = f4_h4(make_float4(s.x*p.x, s.y*p.y, s.z*p.z, s.w*p.w));
        if (i < E_) {
            g_bv[i] = bv_sh[i] + bv_sp[lang*E_ + i];
            g_bo[i] = bo_sh[i] + bo_sp[lang*E_ + i];
        }
    }
}

// ---------------- fp16 GEMM: 256x128 CTA tile, 64x64 warp tile, BKH=64, NS=3 --
// CUTLASS multistage order: wait -> ONE sync -> issue load(it+2) -> compute(it).
// WAIT LADDER (fixed): at entry, issued max = tile it+1 (load happens post-sync),
// so tile `it` is guaranteed complete by CP_WAIT(1) (1 group allowed pending).
#define BM 256
#define BN 128
#define BKH 64
#define NIT (E_/BKH)          // 8
#define A_U4 (BM*8)           // 2048 uint4
#define B_U4 (BN*8)           // 1024 uint4
#define STAGE_U4 (A_U4 + B_U4)
#define GNS 3
#define GEMM_SMEM (GNS*STAGE_U4*16)   // 144 KB

template<int HALF_OUT>
__device__ __forceinline__ void gemm_core(const __half* __restrict__ A,
                                          const __half* __restrict__ W,
                                          const float* __restrict__ bias,
                                          void* __restrict__ Cv,
                                          int bm, int bn, float cs) {
    extern __shared__ uint4 dsm[];
    const int tid  = threadIdx.x;
    const int wid  = tid >> 5;
    const int lane = tid & 31;
    const int wm   = (wid >> 1) * 64;    // 4 M-groups of 64
    const int wn   = (wid & 1) * 64;     // 2 N-groups of 64
    const int grp  = lane >> 2;
    const int t4   = lane & 3;
    const uint32_t sb = smem_u32(dsm);

    float acc[4][8][4];
    #pragma unroll
    for (int i = 0; i < 4; i++)
        #pragma unroll
        for (int j = 0; j < 8; j++)
            #pragma unroll
            for (int q = 0; q < 4; q++) acc[i][j][q] = 0.f;

    auto load_tile = [&](int it, int buf) {
        uint32_t abase = sb + (uint32_t)(buf*STAGE_U4) * 16u;
        uint32_t bbase = abase + (uint32_t)A_U4 * 16u;
        #pragma unroll
        for (int v = 0; v < 8; ++v) {            // A: 2048 chunks
            int c = v*256 + tid;
            int r = c >> 3, ch = c & 7;
            cpa16(abase + (uint32_t)(r*8 + (ch ^ (r & 7))) * 16u,
                  (const uint4*)(A + (size_t)(bm + r)*E_ + it*BKH) + ch);
        }
        #pragma unroll
        for (int v = 0; v < 4; ++v) {            // B: 1024 chunks
            int c = v*256 + tid;
            int r = c >> 3, ch = c & 7;
            cpa16(bbase + (uint32_t)(r*8 + (ch ^ (r & 7))) * 16u,
                  (const uint4*)(W + (size_t)(bn + r)*E_ + it*BKH) + ch);
        }
    };

    load_tile(0, 0); CP_COMMIT();
    load_tile(1, 1); CP_COMMIT();

    for (int it = 0; it < NIT; ++it) {
        // issued max at entry = tile min(it+1, NIT-1); tile `it` done when
        // pending <= (issued_max - it)
        if (it + 1 < NIT) { CP_WAIT(1); }
        else              { CP_WAIT(0); }
        __syncthreads();   // all warps finished compute(it-1); tile `it` visible
        if (it + 2 < NIT) {
            load_tile(it + 2, (it + 2) % GNS);   // buf (it-1)%GNS, free after sync
            CP_COMMIT();
        }

        const uint32_t abase = sb + (uint32_t)((it % GNS)*STAGE_U4) * 16u;
        const uint32_t bbase = abase + (uint32_t)A_U4 * 16u;
        #pragma unroll
        for (int k16 = 0; k16 < 4; ++k16) {
            uint32_t af[4][4];
            #pragma unroll
            for (int mf = 0; mf < 4; ++mf) {
                int row = wm + mf*16 + (lane & 15);
                int ch  = k16*2 + (lane >> 4);
                ldsm4(af[mf][0], af[mf][1], af[mf][2], af[mf][3],
                      abase + (uint32_t)(row*8 + (ch ^ (row & 7))) * 16u);
            }
            uint32_t bf[8][2];
            #pragma unroll
            for (int np = 0; np < 4; ++np) {
                int row = wn + np*16 + (lane & 7) + ((lane >> 4) & 1)*8;
                int ch  = k16*2 + ((lane >> 3) & 1);
                ldsm4(bf[2*np][0], bf[2*np][1], bf[2*np+1][0], bf[2*np+1][1],
                      bbase + (uint32_t)(row*8 + (ch ^ (row & 7))) * 16u);
            }
            #pragma unroll
            for (int mf = 0; mf < 4; ++mf)
                #pragma unroll
                for (int nf = 0; nf < 8; ++nf)
                    mma_f16(acc[mf][nf], af[mf], bf[nf]);
        }
    }

    #pragma unroll
    for (int mf = 0; mf < 4; ++mf) {
        #pragma unroll
        for (int nf = 0; nf < 8; ++nf) {
            int r0 = bm + wm + mf*16 + grp;
            int c0 = bn + wn + nf*8 + t4*2;
            float b0 = bias[c0], b1 = bias[c0 + 1];
            if (HALF_OUT) {
                __half* C = (__half*)Cv;
                *(uint32_t*)(C + (size_t)r0*E_ + c0)     = h2((acc[mf][nf][0] + b0)*cs, (acc[mf][nf][1] + b1)*cs);
                *(uint32_t*)(C + (size_t)(r0+8)*E_ + c0) = h2((acc[mf][nf][2] + b0)*cs, (acc[mf][nf][3] + b1)*cs);
            } else {
                float* C = (float*)Cv;
                float2 v0, v1;
                v0.x = acc[mf][nf][0] + b0; v0.y = acc[mf][nf][1] + b1;
                v1.x = acc[mf][nf][2] + b0; v1.y = acc[mf][nf][3] + b1;
                *(float2*)(C + (size_t)r0*E_ + c0)     = v0;
                *(float2*)(C + (size_t)(r0+8)*E_ + c0) = v1;
            }
        }
    }
}

__global__ __launch_bounds__(256, 1) void gemm_qkv(const __half* Aq, const __half* Ak, const __half* Av,
                                                   const __half* Wq, const __half* Wk, const __half* Wv,
                                                   const float* bq, const float* bk, const float* bv,
                                                   __half* Cq, __half* Ck, __half* Cvp) {
    const int z = blockIdx.z;
    const __half* A = (z == 0) ? Aq : (z == 1) ? Ak : Av;
    const __half* W = (z == 0) ? Wq : (z == 1) ? Wk : Wv;
    const float*  bb = (z == 0) ? bq : (z == 1) ? bk : bv;
    __half*       C = (z == 0) ? Cq : (z == 1) ? Ck : Cvp;
    float cs = (z == 0) ? 0.015625f * 1.44269504088896f : 1.f;
    gemm_core<1>(A, W, bb, C, blockIdx.y * BM, blockIdx.x * BN, cs);
}

__global__ __launch_bounds__(256, 1) void gemm_out(const __half* __restrict__ A,
                                                   const __half* __restrict__ W,
                                                   const float* __restrict__ bias,
                                                   float* __restrict__ C) {
    gemm_core<0>(A, W, bias, C, blockIdx.y * BM, blockIdx.x * BN, 1.f);
}

// ---------------- fp16 flash attention: 32 q-rows/warp, depth-3 pipeline ------
// CUTLASS order: mflag-write -> wait(2) [3 groups in flight at entry] -> ONE
// sync -> issue load(kt+3) -> compute(kt).
#define KVB_U4 (64*8)
#define ANS 4
#define ATT_SMEM (2*ANS*KVB_U4*16 + ANS*64*4)
#define NT (S_/64)

__global__ __launch_bounds__(256, 1) void attn_h(const __half* __restrict__ Q,
                                                 const __half* __restrict__ K,
                                                 const __half* __restrict__ V,
                                                 const int* __restrict__ mask,
                                                 __half* __restrict__ ctx) {
    extern __shared__ uint4 dsm[];
    uint4* sK = dsm;
    uint4* sV = dsm + ANS*KVB_U4;
    float* mflag = (float*)(dsm + 2*ANS*KVB_U4);

    const int bh = blockIdx.x;
    const int b  = bh >> 3;
    const int h  = bh & 7;
    const int q0 = blockIdx.y * 256;
    const int tid  = threadIdx.x;
    const int wid  = tid >> 5;
    const int lane = tid & 31;
    const int grp  = lane >> 2;
    const int t4   = lane & 3;
    const int row0 = wid * 32;
    const uint32_t sKb = smem_u32(sK);
    const uint32_t sVb = smem_u32(sV);

    const size_t kvbase = (size_t)b*S_*E_ + (size_t)h*D_;

    auto load_kv = [&](int kt, int buf) {
        const int key0 = kt * 64;
        #pragma unroll
        for (int v = 0; v < 2; ++v) {
            int c = tid*2 + v;
            int r = c >> 3, ch = c & 7;
            uint32_t off = (uint32_t)(buf*KVB_U4 + r*8 + (ch ^ (r & 7))) * 16u;
            cpa16(sKb + off, (const uint4*)(K + kvbase + (size_t)(key0 + r)*E_) + ch);
            cpa16(sVb + off, (const uint4*)(V + kvbase + (size_t)(key0 + r)*E_) + ch);
        }
    };

    uint32_t qf[2][4][4];
    const __half* qb = Q + ((size_t)b*S_ + q0 + row0)*E_ + h*D_;
    #pragma unroll
    for (int mf = 0; mf < 2; ++mf) {
        #pragma unroll
        for (int k16 = 0; k16 < 4; ++k16) {
            qf[mf][k16][0] = *(const uint32_t*)(qb + (size_t)(mf*16 + grp)*E_     + k16*16 + 2*t4);
            qf[mf][k16][1] = *(const uint32_t*)(qb + (size_t)(mf*16 + grp + 8)*E_ + k16*16 + 2*t4);
            qf[mf][k16][2] = *(const uint32_t*)(qb + (size_t)(mf*16 + grp)*E_     + k16*16 + 2*t4 + 8);
            qf[mf][k16][3] = *(const uint32_t*)(qb + (size_t)(mf*16 + grp + 8)*E_ + k16*16 + 2*t4 + 8);
        }
    }

    float oacc[2][8][4];
    #pragma unroll
    for (int mf = 0; mf < 2; mf++)
        #pragma unroll
        for (int nf = 0; nf < 8; nf++)
            #pragma unroll
            for (int c = 0; c < 4; c++) oacc[mf][nf][c] = 0.f;
    float dacc[2][4] = {{0.f,0.f,0.f,0.f},{0.f,0.f,0.f,0.f}};
    const uint32_t ones2[2] = {0x3C003C00u, 0x3C003C00u};

    // prologue: 3 tiles in flight (depth 3)
    load_kv(0, 0); CP_COMMIT();
    load_kv(1, 1); CP_COMMIT();
    load_kv(2, 2); CP_COMMIT();
    int mq0 = 0, mq1 = 0, mq2 = 0;
    if (tid < 64) {
        mq0 = mask[b*S_ + tid];
        mq1 = mask[b*S_ + 64 + tid];
        mq2 = mask[b*S_ + 128 + tid];
    }

    for (int kt = 0; kt < NT; ++kt) {
        if (tid < 64) mflag[(kt % ANS)*64 + tid] = mq0 ? 0.f : -60000.f;
        mq0 = mq1; mq1 = mq2;
        if (kt + 2 < NT)      { CP_WAIT(2); }
        else if (kt + 1 < NT) { CP_WAIT(1); }
        else                  { CP_WAIT(0); }
        __syncthreads();   // tile kt visible; all warps finished compute(kt-1)
        if (kt + 3 < NT) {
            load_kv(kt + 3, (kt + 3) % ANS);   // buf (kt-1)%ANS, free after sync
            CP_COMMIT();
            if (tid < 64) mq2 = mask[b*S_ + (kt + 3)*64 + tid];
        }

        const uint32_t koff = (uint32_t)((kt % ANS)*KVB_U4) * 16u;
        const float* mf_ = mflag + (kt % ANS)*64;

        float sacc[2][8][4];
        #pragma unroll
        for (int nf = 0; nf < 8; nf++) {
            float2 mo = *(const float2*)&mf_[nf*8 + 2*t4];
            #pragma unroll
            for (int mf = 0; mf < 2; mf++) {
                sacc[mf][nf][0] = mo.x; sacc[mf][nf][1] = mo.y;
                sacc[mf][nf][2] = mo.x; sacc[mf][nf][3] = mo.y;
            }
        }
        #pragma unroll
        for (int k16 = 0; k16 < 4; ++k16) {
            #pragma unroll
            for (int np = 0; np < 4; ++np) {
                uint32_t b0, b1, b2, b3;
                int row = np*16 + (lane & 7) + ((lane >> 4) & 1)*8;
                int ch  = k16*2 + ((lane >> 3) & 1);
                ldsm4(b0, b1, b2, b3, sKb + koff + (uint32_t)(row*8 + (ch ^ (row & 7))) * 16u);
                uint32_t bb0[2] = {b0, b1}, bb1[2] = {b2, b3};
                #pragma unroll
                for (int mf = 0; mf < 2; mf++) {
                    mma_f16(sacc[mf][2*np],   qf[mf][k16], bb0);
                    mma_f16(sacc[mf][2*np+1], qf[mf][k16], bb1);
                }
            }
        }

        uint32_t pf[2][4][4];
        #pragma unroll
        for (int mf = 0; mf < 2; mf++)
            #pragma unroll
            for (int nf = 0; nf < 8; nf++) {
                pf[mf][nf >> 1][(nf & 1) * 2]     = ex2h2(sacc[mf][nf][0], sacc[mf][nf][1]);
                pf[mf][nf >> 1][(nf & 1) * 2 + 1] = ex2h2(sacc[mf][nf][2], sacc[mf][nf][3]);
            }

        #pragma unroll
        for (int k16 = 0; k16 < 4; ++k16) {
            #pragma unroll
            for (int np = 0; np < 4; ++np) {
                uint32_t b0, b1, b2, b3;
                int row = k16*16 + (lane & 7) + ((lane >> 3) & 1)*8;
                int ch  = np*2 + ((lane >> 4) & 1);
                ldsm4t(b0, b1, b2, b3, sVb + koff + (uint32_t)(row*8 + (ch ^ (row & 7))) * 16u);
                uint32_t bb0[2] = {b0, b1}, bb1[2] = {b2, b3};
                #pragma unroll
                for (int mf = 0; mf < 2; mf++) {
                    mma_f16(oacc[mf][2*np],   pf[mf][k16], bb0);
                    mma_f16(oacc[mf][2*np+1], pf[mf][k16], bb1);
                }
            }
            #pragma unroll
            for (int mf = 0; mf < 2; mf++)
                mma_f16(dacc[mf], pf[mf][k16], ones2);
        }
    }

    #pragma unroll
    for (int mf = 0; mf < 2; mf++) {
        float i0 = 1.f / dacc[mf][0], i1 = 1.f / dacc[mf][2];
        __half* op = ctx + ((size_t)b*S_ + q0 + row0 + mf*16)*E_ + h*D_;
        #pragma unroll
        for (int nf = 0; nf < 8; nf++) {
            int c0 = nf*8 + 2*t4;
            *(uint32_t*)(op + (size_t)grp*E_ + c0)     = h2(oacc[mf][nf][0]*i0, oacc[mf][nf][1]*i0);
            *(uint32_t*)(op + (size_t)(grp+8)*E_ + c0) = h2(oacc[mf][nf][2]*i1, oacc[mf][nf][3]*i1);
        }
    }
}

// ---------------- launch ----------------
extern "C" void kernel_launch(void* const* d_in, const int* in_sizes, int n_in,
                              void* d_out, int out_size) {
    const float* q      = (const float*)d_in[0];
    const float* k      = (const float*)d_in[1];
    const float* v      = (const float*)d_in[2];
    const float* Wq     = (const float*)d_in[3];
    const float* bq     = (const float*)d_in[4];
    const float* Wk     = (const float*)d_in[5];
    const float* bk     = (const float*)d_in[6];
    const float* Wv_sh  = (const float*)d_in[7];
    const float* Wv_sp  = (const float*)d_in[8];
    const float* bv_sh  = (const float*)d_in[9];
    const float* bv_sp  = (const float*)d_in[10];
    const float* Wo_sh  = (const float*)d_in[11];
    const float* Wo_sp  = (const float*)d_in[12];
    const float* bo_sh  = (const float*)d_in[13];
    const float* bo_sp  = (const float*)d_in[14];
    const int*   mask   = (const int*)d_in[15];
    const int*   lang   = (const int*)d_in[16];

    void *pqh, *pkh, *pvh, *pQh, *pKh, *pVh, *pctx;
    void *pWq, *pWk, *pWv, *pWo, *pbv, *pbo;
    cudaGetSymbolAddress(&pqh, g_qh);
    cudaGetSymbolAddress(&pkh, g_kh);
    cudaGetSymbolAddress(&pvh, g_vh);
    cudaGetSymbolAddress(&pQh, g_Qh);
    cudaGetSymbolAddress(&pKh, g_Kh);
    cudaGetSymbolAddress(&pVh, g_Vh);
    cudaGetSymbolAddress(&pctx, g_ctxh);
    cudaGetSymbolAddress(&pWq, g_Wqh);
    cudaGetSymbolAddress(&pWk, g_Wkh);
    cudaGetSymbolAddress(&pWv, g_Wvh);
    cudaGetSymbolAddress(&pWo, g_Woh);
    cudaGetSymbolAddress(&pbv, g_bv);
    cudaGetSymbolAddress(&pbo, g_bo);

    static int attr_set = 0;
    if (!attr_set) {
        cudaFuncSetAttribute(gemm_qkv, cudaFuncAttributeMaxDynamicSharedMemorySize, GEMM_SMEM);
        cudaFuncSetAttribute(gemm_out, cudaFuncAttributeMaxDynamicSharedMemorySize, GEMM_SMEM);
        cudaFuncSetAttribute(attn_h,   cudaFuncAttributeMaxDynamicSharedMemorySize, ATT_SMEM);
        attr_set = 1;
    }

    prep_all<<<4096 + 256, 256>>>(q, k, v, Wq, Wk, Wv_sh, Wv_sp, Wo_sh, Wo_sp,
                                  bv_sh, bv_sp, bo_sh, bo_sp, lang);

    dim3 gq(E_/BN, M_/BM, 3);   // (4, 64, 3)
    gemm_qkv<<<gq, 256, GEMM_SMEM>>>((const __half*)pqh, (const __half*)pkh, (const __half*)pvh,
                                     (const __half*)pWq, (const __half*)pWk, (const __half*)pWv,
                                     bq, bk, (const float*)pbv,
                                     (__half*)pQh, (__half*)pKh, (__half*)pVh);

    attn_h<<<dim3(B_*H_, S_/256), 256, ATT_SMEM>>>((const __half*)pQh, (const __half*)pKh,
                                                   (const __half*)pVh, mask, (__half*)pctx);

    dim3 gg(E_/BN, M_/BM);   // (4, 64)
    gemm_out<<<gg, 256, GEMM_SMEM>>>((const __half*)pctx, (const __half*)pWo,
                                     (const float*)pbo, (float*)d_out);
}

// round 15
// speedup vs baseline: 1.6667x; 1.0001x over previous
#include <cuda_runtime.h>
#include <cuda_fp16.h>
#include <cstdint>

#define B_ 16
#define S_ 1024
#define E_ 512
#define H_ 8
#define D_ 64
#define L_ 4
#define M_ (B_*S_)   // 16384 rows

// ---------------- device scratch (no allocations allowed) ----------------
__device__ __half g_qh[M_*E_];
__device__ __half g_kh[M_*E_];
__device__ __half g_vh[M_*E_];
__device__ __half g_Qh[M_*E_];
__device__ __half g_Kh[M_*E_];
__device__ __half g_Vh[M_*E_];
__device__ __half g_ctxh[M_*E_];
__device__ __half g_Wqh[E_*E_];
__device__ __half g_Wkh[E_*E_];
__device__ __half g_Wvh[E_*E_];
__device__ __half g_Woh[E_*E_];
__device__ float  g_bv[E_];
__device__ float  g_bo[E_];

// ---------------- PTX helpers ----------------
__device__ __forceinline__ uint32_t smem_u32(const void* p) {
    uint32_t a;
    asm("{ .reg .u64 t; cvta.to.shared.u64 t, %1; cvt.u32.u64 %0, t; }" : "=r"(a) : "l"(p));
    return a;
}
__device__ __forceinline__ void mma_f16(float* c, const uint32_t* a, const uint32_t* b) {
    asm volatile(
        "mma.sync.aligned.m16n8k16.row.col.f32.f16.f16.f32 "
        "{%0,%1,%2,%3}, {%4,%5,%6,%7}, {%8,%9}, {%0,%1,%2,%3};\n"
        : "+f"(c[0]), "+f"(c[1]), "+f"(c[2]), "+f"(c[3])
        : "r"(a[0]), "r"(a[1]), "r"(a[2]), "r"(a[3]), "r"(b[0]), "r"(b[1]));
}
__device__ __forceinline__ void ldsm4(uint32_t& r0, uint32_t& r1, uint32_t& r2, uint32_t& r3,
                                      uint32_t addr) {
    asm volatile("ldmatrix.sync.aligned.m8n8.x4.shared.b16 {%0,%1,%2,%3}, [%4];\n"
                 : "=r"(r0), "=r"(r1), "=r"(r2), "=r"(r3) : "r"(addr));
}
__device__ __forceinline__ void ldsm4t(uint32_t& r0, uint32_t& r1, uint32_t& r2, uint32_t& r3,
                                       uint32_t addr) {
    asm volatile("ldmatrix.sync.aligned.m8n8.x4.trans.shared.b16 {%0,%1,%2,%3}, [%4];\n"
                 : "=r"(r0), "=r"(r1), "=r"(r2), "=r"(r3) : "r"(addr));
}
__device__ __forceinline__ void cpa16(uint32_t d, const void* s) {
    asm volatile("cp.async.ca.shared.global [%0], [%1], 16;\n" :: "r"(d), "l"(s));
}
#define CP_COMMIT() asm volatile("cp.async.commit_group;\n" ::: "memory")
#define CP_WAIT(N)  asm volatile("cp.async.wait_group %0;\n" :: "n"(N) : "memory")

__device__ __forceinline__ uint32_t h2(float a, float b) {
    __half2 v = __floats2half2_rn(a, b);
    return *(uint32_t*)&v;
}
// pack (lo,hi) to f16x2 then 2^x elementwise
__device__ __forceinline__ uint32_t ex2h2(float lo, float hi) {
    uint32_t p, r;
    asm("cvt.rn.f16x2.f32 %0, %1, %2;" : "=r"(p) : "f"(hi), "f"(lo));
    asm("ex2.approx.f16x2 %0, %1;" : "=r"(r) : "r"(p));
    return r;
}
__device__ __forceinline__ uint2 f4_h4(float4 a) {
    uint2 r;
    r.x = h2(a.x, a.y);
    r.y = h2(a.z, a.w);
    return r;
}

// ---------------- prep: single merged fp32 -> fp16 conversion kernel ----------
__global__ __launch_bounds__(256) void prep_all(
        const float* __restrict__ q, const float* __restrict__ k, const float* __restrict__ v,
        const float* __restrict__ Wq, const float* __restrict__ Wk,
        const float* __restrict__ Wv_sh, const float* __restrict__ Wv_sp,
        const float* __restrict__ Wo_sh, const float* __restrict__ Wo_sp,
        const float* __restrict__ bv_sh, const float* __restrict__ bv_sp,
        const float* __restrict__ bo_sh, const float* __restrict__ bo_sp,
        const int* __restrict__ langp) {
    int bid = blockIdx.x;
    if (bid < 4096) {
        int t = bid * 256 + threadIdx.x;
        int j = t * 2;
        uint4 o;
        uint2 a, b;
        a = f4_h4(((const float4*)q)[j]); b = f4_h4(((const float4*)q)[j+1]);
        o.x = a.x; o.y = a.y; o.z = b.x; o.w = b.y;
        ((uint4*)g_qh)[t] = o;
        a = f4_h4(((const float4*)k)[j]); b = f4_h4(((const float4*)k)[j+1]);
        o.x = a.x; o.y = a.y; o.z = b.x; o.w = b.y;
        ((uint4*)g_kh)[t] = o;
        a = f4_h4(((const float4*)v)[j]); b = f4_h4(((const float4*)v)[j+1]);
        o.x = a.x; o.y = a.y; o.z = b.x; o.w = b.y;
        ((uint4*)g_vh)[t] = o;
    } else {
        int lang = langp[0];
        int i = (bid - 4096) * 256 + threadIdx.x;
        ((uint2*)g_Wqh)[i] = f4_h4(((const float4*)Wq)[i]);
        ((uint2*)g_Wkh)[i] = f4_h4(((const float4*)Wk)[i]);
        size_t so = (size_t)lang * (E_*E_/4);
        float4 s, p;
        s = ((const float4*)Wv_sh)[i];  p = ((const float4*)Wv_sp)[so + i];
        ((uint2*)g_Wvh)[i] = f4_h4(make_float4(s.x*p.x, s.y*p.y, s.z*p.z, s.w*p.w));
        s = ((const float4*)Wo_sh)[i];  p = ((const float4*)Wo_sp)[so + i];
        ((uint2*)g_Woh)[i] = f4_h4(make_float4(s.x*p.x, s.y*p.y, s.z*p.z, s.w*p.w));
        if (i < E_) {
            g_bv[i] = bv_sh[i] + bv_sp[lang*E_ + i];
            g_bo[i] = bo_sh[i] + bo_sp[lang*E_ + i];
        }
    }
}

// ---------------- fp16 GEMM: 256x128 CTA, 64x32 warp tile, 512 thr, GNS=4 -----
// 16 warps (4Mx4N) = 4 warps/SMSP for latency hiding. Depth-3 prefetch,
// attention-style ladder: prologue 3 tiles, wait(2)/sync/issue(it+3).
#define BM 256
#define BN 128
#define BKH 64
#define NIT (E_/BKH)          // 8
#define A_U4 (BM*8)           // 2048 uint4
#define B_U4 (BN*8)           // 1024 uint4
#define STAGE_U4 (A_U4 + B_U4)
#define GNS 4
#define GEMM_SMEM (GNS*STAGE_U4*16)   // 192 KB
#define GTH 512

template<int HALF_OUT>
__device__ __forceinline__ void gemm_core(const __half* __restrict__ A,
                                          const __half* __restrict__ W,
                                          const float* __restrict__ bias,
                                          void* __restrict__ Cv,
                                          int bm, int bn, float cs) {
    extern __shared__ uint4 dsm[];
    const int tid  = threadIdx.x;
    const int wid  = tid >> 5;
    const int lane = tid & 31;
    const int wm   = (wid >> 2) * 64;    // 4 M-groups of 64
    const int wn   = (wid & 3) * 32;     // 4 N-groups of 32
    const int grp  = lane >> 2;
    const int t4   = lane & 3;
    const uint32_t sb = smem_u32(dsm);

    float acc[4][4][4];
    #pragma unroll
    for (int i = 0; i < 4; i++)
        #pragma unroll
        for (int j = 0; j < 4; j++)
            #pragma unroll
            for (int q = 0; q < 4; q++) acc[i][j][q] = 0.f;

    auto load_tile = [&](int it, int buf) {
        uint32_t abase = sb + (uint32_t)(buf*STAGE_U4) * 16u;
        uint32_t bbase = abase + (uint32_t)A_U4 * 16u;
        #pragma unroll
        for (int v = 0; v < 4; ++v) {            // A: 2048 chunks, 512 thr
            int c = v*GTH + tid;
            int r = c >> 3, ch = c & 7;
            cpa16(abase + (uint32_t)(r*8 + (ch ^ (r & 7))) * 16u,
                  (const uint4*)(A + (size_t)(bm + r)*E_ + it*BKH) + ch);
        }
        #pragma unroll
        for (int v = 0; v < 2; ++v) {            // B: 1024 chunks
            int c = v*GTH + tid;
            int r = c >> 3, ch = c & 7;
            cpa16(bbase + (uint32_t)(r*8 + (ch ^ (r & 7))) * 16u,
                  (const uint4*)(W + (size_t)(bn + r)*E_ + it*BKH) + ch);
        }
    };

    load_tile(0, 0); CP_COMMIT();
    load_tile(1, 1); CP_COMMIT();
    load_tile(2, 2); CP_COMMIT();

    for (int it = 0; it < NIT; ++it) {
        // issued max at entry = tile min(it+2, NIT-1) -> allowed pending ladder:
        if (it + 2 < NIT)      { CP_WAIT(2); }
        else if (it + 1 < NIT) { CP_WAIT(1); }
        else                   { CP_WAIT(0); }
        __syncthreads();   // tile `it` visible; all warps finished compute(it-1)
        if (it + 3 < NIT) {
            load_tile(it + 3, (it + 3) % GNS);   // buf (it-1)%GNS, free after sync
            CP_COMMIT();
        }

        const uint32_t abase = sb + (uint32_t)((it % GNS)*STAGE_U4) * 16u;
        const uint32_t bbase = abase + (uint32_t)A_U4 * 16u;
        #pragma unroll
        for (int k16 = 0; k16 < 4; ++k16) {
            uint32_t af[4][4];
            #pragma unroll
            for (int mf = 0; mf < 4; ++mf) {
                int row = wm + mf*16 + (lane & 15);
                int ch  = k16*2 + (lane >> 4);
                ldsm4(af[mf][0], af[mf][1], af[mf][2], af[mf][3],
                      abase + (uint32_t)(row*8 + (ch ^ (row & 7))) * 16u);
            }
            uint32_t bf[4][2];
            #pragma unroll
            for (int np = 0; np < 2; ++np) {
                int row = wn + np*16 + (lane & 7) + ((lane >> 4) & 1)*8;
                int ch  = k16*2 + ((lane >> 3) & 1);
                ldsm4(bf[2*np][0], bf[2*np][1], bf[2*np+1][0], bf[2*np+1][1],
                      bbase + (uint32_t)(row*8 + (ch ^ (row & 7))) * 16u);
            }
            #pragma unroll
            for (int mf = 0; mf < 4; ++mf)
                #pragma unroll
                for (int nf = 0; nf < 4; ++nf)
                    mma_f16(acc[mf][nf], af[mf], bf[nf]);
        }
    }

    #pragma unroll
    for (int mf = 0; mf < 4; ++mf) {
        #pragma unroll
        for (int nf = 0; nf < 4; ++nf) {
            int r0 = bm + wm + mf*16 + grp;
            int c0 = bn + wn + nf*8 + t4*2;
            float b0 = bias[c0], b1 = bias[c0 + 1];
            if (HALF_OUT) {
                __half* C = (__half*)Cv;
                *(uint32_t*)(C + (size_t)r0*E_ + c0)     = h2((acc[mf][nf][0] + b0)*cs, (acc[mf][nf][1] + b1)*cs);
                *(uint32_t*)(C + (size_t)(r0+8)*E_ + c0) = h2((acc[mf][nf][2] + b0)*cs, (acc[mf][nf][3] + b1)*cs);
            } else {
                float* C = (float*)Cv;
                float2 v0, v1;
                v0.x = acc[mf][nf][0] + b0; v0.y = acc[mf][nf][1] + b1;
                v1.x = acc[mf][nf][2] + b0; v1.y = acc[mf][nf][3] + b1;
                *(float2*)(C + (size_t)r0*E_ + c0)     = v0;
                *(float2*)(C + (size_t)(r0+8)*E_ + c0) = v1;
            }
        }
    }
}

__global__ __launch_bounds__(GTH, 1) void gemm_qkv(const __half* Aq, const __half* Ak, const __half* Av,
                                                   const __half* Wq, const __half* Wk, const __half* Wv,
                                                   const float* bq, const float* bk, const float* bv,
                                                   __half* Cq, __half* Ck, __half* Cvp) {
    const int z = blockIdx.z;
    const __half* A = (z == 0) ? Aq : (z == 1) ? Ak : Av;
    const __half* W = (z == 0) ? Wq : (z == 1) ? Wk : Wv;
    const float*  bb = (z == 0) ? bq : (z == 1) ? bk : bv;
    __half*       C = (z == 0) ? Cq : (z == 1) ? Ck : Cvp;
    float cs = (z == 0) ? 0.015625f * 1.44269504088896f : 1.f;
    gemm_core<1>(A, W, bb, C, blockIdx.y * BM, blockIdx.x * BN, cs);
}

__global__ __launch_bounds__(GTH, 1) void gemm_out(const __half* __restrict__ A,
                                                   const __half* __restrict__ W,
                                                   const float* __restrict__ bias,
                                                   float* __restrict__ C) {
    gemm_core<0>(A, W, bias, C, blockIdx.y * BM, blockIdx.x * BN, 1.f);
}

// ---------------- fp16 flash attention: 32 q-rows/warp, depth-3 (R14 proven) --
#define KVB_U4 (64*8)
#define ANS 4
#define ATT_SMEM (2*ANS*KVB_U4*16 + ANS*64*4)
#define NT (S_/64)

__global__ __launch_bounds__(256, 1) void attn_h(const __half* __restrict__ Q,
                                                 const __half* __restrict__ K,
                                                 const __half* __restrict__ V,
                                                 const int* __restrict__ mask,
                                                 __half* __restrict__ ctx) {
    extern __shared__ uint4 dsm[];
    uint4* sK = dsm;
    uint4* sV = dsm + ANS*KVB_U4;
    float* mflag = (float*)(dsm + 2*ANS*KVB_U4);

    const int bh = blockIdx.x;
    const int b  = bh >> 3;
    const int h  = bh & 7;
    const int q0 = blockIdx.y * 256;
    const int tid  = threadIdx.x;
    const int wid  = tid >> 5;
    const int lane = tid & 31;
    const int grp  = lane >> 2;
    const int t4   = lane & 3;
    const int row0 = wid * 32;
    const uint32_t sKb = smem_u32(sK);
    const uint32_t sVb = smem_u32(sV);

    const size_t kvbase = (size_t)b*S_*E_ + (size_t)h*D_;

    auto load_kv = [&](int kt, int buf) {
        const int key0 = kt * 64;
        #pragma unroll
        for (int v = 0; v < 2; ++v) {
            int c = tid*2 + v;
            int r = c >> 3, ch = c & 7;
            uint32_t off = (uint32_t)(buf*KVB_U4 + r*8 + (ch ^ (r & 7))) * 16u;
            cpa16(sKb + off, (const uint4*)(K + kvbase + (size_t)(key0 + r)*E_) + ch);
            cpa16(sVb + off, (const uint4*)(V + kvbase + (size_t)(key0 + r)*E_) + ch);
        }
    };

    uint32_t qf[2][4][4];
    const __half* qb = Q + ((size_t)b*S_ + q0 + row0)*E_ + h*D_;
    #pragma unroll
    for (int mf = 0; mf < 2; ++mf) {
        #pragma unroll
        for (int k16 = 0; k16 < 4; ++k16) {
            qf[mf][k16][0] = *(const uint32_t*)(qb + (size_t)(mf*16 + grp)*E_     + k16*16 + 2*t4);
            qf[mf][k16][1] = *(const uint32_t*)(qb + (size_t)(mf*16 + grp + 8)*E_ + k16*16 + 2*t4);
            qf[mf][k16][2] = *(const uint32_t*)(qb + (size_t)(mf*16 + grp)*E_     + k16*16 + 2*t4 + 8);
            qf[mf][k16][3] = *(const uint32_t*)(qb + (size_t)(mf*16 + grp + 8)*E_ + k16*16 + 2*t4 + 8);
        }
    }

    float oacc[2][8][4];
    #pragma unroll
    for (int mf = 0; mf < 2; mf++)
        #pragma unroll
        for (int nf = 0; nf < 8; nf++)
            #pragma unroll
            for (int c = 0; c < 4; c++) oacc[mf][nf][c] = 0.f;
    float dacc[2][4] = {{0.f,0.f,0.f,0.f},{0.f,0.f,0.f,0.f}};
    const uint32_t ones2[2] = {0x3C003C00u, 0x3C003C00u};

    // prologue: 3 tiles in flight (depth 3)
    load_kv(0, 0); CP_COMMIT();
    load_kv(1, 1); CP_COMMIT();
    load_kv(2, 2); CP_COMMIT();
    int mq0 = 0, mq1 = 0, mq2 = 0;
    if (tid < 64) {
        mq0 = mask[b*S_ + tid];
        mq1 = mask[b*S_ + 64 + tid];
        mq2 = mask[b*S_ + 128 + tid];
    }

    for (int kt = 0; kt < NT; ++kt) {
        if (tid < 64) mflag[(kt % ANS)*64 + tid] = mq0 ? 0.f : -60000.f;
        mq0 = mq1; mq1 = mq2;
        if (kt + 2 < NT)      { CP_WAIT(2); }
        else if (kt + 1 < NT) { CP_WAIT(1); }
        else                  { CP_WAIT(0); }
        __syncthreads();   // tile kt visible; all warps finished compute(kt-1)
        if (kt + 3 < NT) {
            load_kv(kt + 3, (kt + 3) % ANS);   // buf (kt-1)%ANS, free after sync
            CP_COMMIT();
            if (tid < 64) mq2 = mask[b*S_ + (kt + 3)*64 + tid];
        }

        const uint32_t koff = (uint32_t)((kt % ANS)*KVB_U4) * 16u;
        const float* mf_ = mflag + (kt % ANS)*64;

        float sacc[2][8][4];
        #pragma unroll
        for (int nf = 0; nf < 8; nf++) {
            float2 mo = *(const float2*)&mf_[nf*8 + 2*t4];
            #pragma unroll
            for (int mf = 0; mf < 2; mf++) {
                sacc[mf][nf][0] = mo.x; sacc[mf][nf][1] = mo.y;
                sacc[mf][nf][2] = mo.x; sacc[mf][nf][3] = mo.y;
            }
        }
        #pragma unroll
        for (int k16 = 0; k16 < 4; ++k16) {
            #pragma unroll
            for (int np = 0; np < 4; ++np) {
                uint32_t b0, b1, b2, b3;
                int row = np*16 + (lane & 7) + ((lane >> 4) & 1)*8;
                int ch  = k16*2 + ((lane >> 3) & 1);
                ldsm4(b0, b1, b2, b3, sKb + koff + (uint32_t)(row*8 + (ch ^ (row & 7))) * 16u);
                uint32_t bb0[2] = {b0, b1}, bb1[2] = {b2, b3};
                #pragma unroll
                for (int mf = 0; mf < 2; mf++) {
                    mma_f16(sacc[mf][2*np],   qf[mf][k16], bb0);
                    mma_f16(sacc[mf][2*np+1], qf[mf][k16], bb1);
                }
            }
        }

        uint32_t pf[2][4][4];
        #pragma unroll
        for (int mf = 0; mf < 2; mf++)
            #pragma unroll
            for (int nf = 0; nf < 8; nf++) {
                pf[mf][nf >> 1][(nf & 1) * 2]     = ex2h2(sacc[mf][nf][0], sacc[mf][nf][1]);
                pf[mf][nf >> 1][(nf & 1) * 2 + 1] = ex2h2(sacc[mf][nf][2], sacc[mf][nf][3]);
            }

        #pragma unroll
        for (int k16 = 0; k16 < 4; ++k16) {
            #pragma unroll
            for (int np = 0; np < 4; ++np) {
                uint32_t b0, b1, b2, b3;
                int row = k16*16 + (lane & 7) + ((lane >> 3) & 1)*8;
                int ch  = np*2 + ((lane >> 4) & 1);
                ldsm4t(b0, b1, b2, b3, sVb + koff + (uint32_t)(row*8 + (ch ^ (row & 7))) * 16u);
                uint32_t bb0[2] = {b0, b1}, bb1[2] = {b2, b3};
                #pragma unroll
                for (int mf = 0; mf < 2; mf++) {
                    mma_f16(oacc[mf][2*np],   pf[mf][k16], bb0);
                    mma_f16(oacc[mf][2*np+1], pf[mf][k16], bb1);
                }
            }
            #pragma unroll
            for (int mf = 0; mf < 2; mf++)
                mma_f16(dacc[mf], pf[mf][k16], ones2);
        }
    }

    #pragma unroll
    for (int mf = 0; mf < 2; mf++) {
        float i0 = 1.f / dacc[mf][0], i1 = 1.f / dacc[mf][2];
        __half* op = ctx + ((size_t)b*S_ + q0 + row0 + mf*16)*E_ + h*D_;
        #pragma unroll
        for (int nf = 0; nf < 8; nf++) {
            int c0 = nf*8 + 2*t4;
            *(uint32_t*)(op + (size_t)grp*E_ + c0)     = h2(oacc[mf][nf][0]*i0, oacc[mf][nf][1]*i0);
            *(uint32_t*)(op + (size_t)(grp+8)*E_ + c0) = h2(oacc[mf][nf][2]*i1, oacc[mf][nf][3]*i1);
        }
    }
}

// ---------------- launch ----------------
extern "C" void kernel_launch(void* const* d_in, const int* in_sizes, int n_in,
                              void* d_out, int out_size) {
    const float* q      = (const float*)d_in[0];
    const float* k      = (const float*)d_in[1];
    const float* v      = (const float*)d_in[2];
    const float* Wq     = (const float*)d_in[3];
    const float* bq     = (const float*)d_in[4];
    const float* Wk     = (const float*)d_in[5];
    const float* bk     = (const float*)d_in[6];
    const float* Wv_sh  = (const float*)d_in[7];
    const float* Wv_sp  = (const float*)d_in[8];
    const float* bv_sh  = (const float*)d_in[9];
    const float* bv_sp  = (const float*)d_in[10];
    const float* Wo_sh  = (const float*)d_in[11];
    const float* Wo_sp  = (const float*)d_in[12];
    const float* bo_sh  = (const float*)d_in[13];
    const float* bo_sp  = (const float*)d_in[14];
    const int*   mask   = (const int*)d_in[15];
    const int*   lang   = (const int*)d_in[16];

    void *pqh, *pkh, *pvh, *pQh, *pKh, *pVh, *pctx;
    void *pWq, *pWk, *pWv, *pWo, *pbv, *pbo;
    cudaGetSymbolAddress(&pqh, g_qh);
    cudaGetSymbolAddress(&pkh, g_kh);
    cudaGetSymbolAddress(&pvh, g_vh);
    cudaGetSymbolAddress(&pQh, g_Qh);
    cudaGetSymbolAddress(&pKh, g_Kh);
    cudaGetSymbolAddress(&pVh, g_Vh);
    cudaGetSymbolAddress(&pctx, g_ctxh);
    cudaGetSymbolAddress(&pWq, g_Wqh);
    cudaGetSymbolAddress(&pWk, g_Wkh);
    cudaGetSymbolAddress(&pWv, g_Wvh);
    cudaGetSymbolAddress(&pWo, g_Woh);
    cudaGetSymbolAddress(&pbv, g_bv);
    cudaGetSymbolAddress(&pbo, g_bo);

    static int attr_set = 0;
    if (!attr_set) {
        cudaFuncSetAttribute(gemm_qkv, cudaFuncAttributeMaxDynamicSharedMemorySize, GEMM_SMEM);
        cudaFuncSetAttribute(gemm_out, cudaFuncAttributeMaxDynamicSharedMemorySize, GEMM_SMEM);
        cudaFuncSetAttribute(attn_h,   cudaFuncAttributeMaxDynamicSharedMemorySize, ATT_SMEM);
        attr_set = 1;
    }

    prep_all<<<4096 + 256, 256>>>(q, k, v, Wq, Wk, Wv_sh, Wv_sp, Wo_sh, Wo_sp,
                                  bv_sh, bv_sp, bo_sh, bo_sp, lang);

    dim3 gq(E_/BN, M_/BM, 3);   // (4, 64, 3)
    gemm_qkv<<<gq, GTH, GEMM_SMEM>>>((const __half*)pqh, (const __half*)pkh, (const __half*)pvh,
                                     (const __half*)pWq, (const __half*)pWk, (const __half*)pWv,
                                     bq, bk, (const float*)pbv,
                                     (__half*)pQh, (__half*)pKh, (__half*)pVh);

    attn_h<<<dim3(B_*H_, S_/256), 256, ATT_SMEM>>>((const __half*)pQh, (const __half*)pKh,
                                                   (const __half*)pVh, mask, (__half*)pctx);

    dim3 gg(E_/BN, M_/BM);   // (4, 64)
    gemm_out<<<gg, GTH, GEMM_SMEM>>>((const __half*)pctx, (const __half*)pWo,
                                     (const float*)pbo, (float*)d_out);
}

// round 16
// speedup vs baseline: 1.6733x; 1.0040x over previous
#include <cuda_runtime.h>
#include <cuda_fp16.h>
#include <cstdint>

#define B_ 16
#define S_ 1024
#define E_ 512
#define H_ 8
#define D_ 64
#define L_ 4
#define M_ (B_*S_)   // 16384 rows

// ---------------- device scratch (no allocations allowed) ----------------
__device__ __half g_qh[M_*E_];
__device__ __half g_kh[M_*E_];
__device__ __half g_vh[M_*E_];
__device__ __half g_Qh[M_*E_];
__device__ __half g_Kh[M_*E_];
__device__ __half g_Vh[M_*E_];
__device__ __half g_ctxh[M_*E_];
__device__ __half g_Wqh[E_*E_];
__device__ __half g_Wkh[E_*E_];
__device__ __half g_Wvh[E_*E_];
__device__ __half g_Woh[E_*E_];
__device__ float  g_bv[E_];
__device__ float  g_bo[E_];

// ---------------- PTX helpers ----------------
__device__ __forceinline__ uint32_t smem_u32(const void* p) {
    uint32_t a;
    asm("{ .reg .u64 t; cvta.to.shared.u64 t, %1; cvt.u32.u64 %0, t; }" : "=r"(a) : "l"(p));
    return a;
}
__device__ __forceinline__ void mma_f16(float* c, const uint32_t* a, const uint32_t* b) {
    asm volatile(
        "mma.sync.aligned.m16n8k16.row.col.f32.f16.f16.f32 "
        "{%0,%1,%2,%3}, {%4,%5,%6,%7}, {%8,%9}, {%0,%1,%2,%3};\n"
        : "+f"(c[0]), "+f"(c[1]), "+f"(c[2]), "+f"(c[3])
        : "r"(a[0]), "r"(a[1]), "r"(a[2]), "r"(a[3]), "r"(b[0]), "r"(b[1]));
}
__device__ __forceinline__ void ldsm4(uint32_t& r0, uint32_t& r1, uint32_t& r2, uint32_t& r3,
                                      uint32_t addr) {
    asm volatile("ldmatrix.sync.aligned.m8n8.x4.shared.b16 {%0,%1,%2,%3}, [%4];\n"
                 : "=r"(r0), "=r"(r1), "=r"(r2), "=r"(r3) : "r"(addr));
}
__device__ __forceinline__ void ldsm4t(uint32_t& r0, uint32_t& r1, uint32_t& r2, uint32_t& r3,
                                       uint32_t addr) {
    asm volatile("ldmatrix.sync.aligned.m8n8.x4.trans.shared.b16 {%0,%1,%2,%3}, [%4];\n"
                 : "=r"(r0), "=r"(r1), "=r"(r2), "=r"(r3) : "r"(addr));
}
__device__ __forceinline__ void cpa16(uint32_t d, const void* s) {
    asm volatile("cp.async.ca.shared.global [%0], [%1], 16;\n" :: "r"(d), "l"(s));
}
#define CP_COMMIT() asm volatile("cp.async.commit_group;\n" ::: "memory")
#define CP_WAIT(N)  asm volatile("cp.async.wait_group %0;\n" :: "n"(N) : "memory")

__device__ __forceinline__ uint32_t h2(float a, float b) {
    __half2 v = __floats2half2_rn(a, b);
    return *(uint32_t*)&v;
}
// pack (lo,hi) to f16x2 then 2^x elementwise
__device__ __forceinline__ uint32_t ex2h2(float lo, float hi) {
    uint32_t p, r;
    asm("cvt.rn.f16x2.f32 %0, %1, %2;" : "=r"(p) : "f"(hi), "f"(lo));
    asm("ex2.approx.f16x2 %0, %1;" : "=r"(r) : "r"(p));
    return r;
}
__device__ __forceinline__ uint2 f4_h4(float4 a) {
    uint2 r;
    r.x = h2(a.x, a.y);
    r.y = h2(a.z, a.w);
    return r;
}

// ---------------- prep: single merged fp32 -> fp16 conversion kernel ----------
__global__ __launch_bounds__(256) void prep_all(
        const float* __restrict__ q, const float* __restrict__ k, const float* __restrict__ v,
        const float* __restrict__ Wq, const float* __restrict__ Wk,
        const float* __restrict__ Wv_sh, const float* __restrict__ Wv_sp,
        const float* __restrict__ Wo_sh, const float* __restrict__ Wo_sp,
        const float* __restrict__ bv_sh, const float* __restrict__ bv_sp,
        const float* __restrict__ bo_sh, const float* __restrict__ bo_sp,
        const int* __restrict__ langp) {
    int bid = blockIdx.x;
    if (bid < 4096) {
        int t = bid * 256 + threadIdx.x;
        int j = t * 2;
        uint4 o;
        uint2 a, b;
        a = f4_h4(((const float4*)q)[j]); b = f4_h4(((const float4*)q)[j+1]);
        o.x = a.x; o.y = a.y; o.z = b.x; o.w = b.y;
        ((uint4*)g_qh)[t] = o;
        a = f4_h4(((const float4*)k)[j]); b = f4_h4(((const float4*)k)[j+1]);
        o.x = a.x; o.y = a.y; o.z = b.x; o.w = b.y;
        ((uint4*)g_kh)[t] = o;
        a = f4_h4(((const float4*)v)[j]); b = f4_h4(((const float4*)v)[j+1]);
        o.x = a.x; o.y = a.y; o.z = b.x; o.w = b.y;
        ((uint4*)g_vh)[t] = o;
    } else {
        int lang = langp[0];
        int i = (bid - 4096) * 256 + threadIdx.x;
        ((uint2*)g_Wqh)[i] = f4_h4(((const float4*)Wq)[i]);
        ((uint2*)g_Wkh)[i] = f4_h4(((const float4*)Wk)[i]);
        size_t so = (size_t)lang * (E_*E_/4);
        float4 s, p;
        s = ((const float4*)Wv_sh)[i];  p = ((const float4*)Wv_sp)[so + i];
        ((uint2*)g_Wvh)[i] = f4_h4(make_float4(s.x*p.x, s.y*p.y, s.z*p.z, s.w*p.w));
        s = ((const float4*)Wo_sh)[i];  p = ((const float4*)Wo_sp)[so + i];
        ((uint2*)g_Woh)[i] = f4_h4(make_float4(s.x*p.x, s.y*p.y, s.z*p.z, s.w*p.w));
        if (i < E_) {
            g_bv[i] = bv_sh[i] + bv_sp[lang*E_ + i];
            g_bo[i] = bo_sh[i] + bo_sp[lang*E_ + i];
        }
    }
}

// ---------------- fp16 GEMM: 256x128 CTA, 64x64 warp tile, 256 thr, GNS=3 -----
// Fragment DOUBLE BUFFERING across k16: ldsm for k16+1 issued before the 32 MMAs
// of k16, hiding the ldsm->mma dependency wall (the suspected 40%-tensor cap).
#define BM 256
#define BN 128
#define BKH 64
#define NIT (E_/BKH)          // 8
#define A_U4 (BM*8)           // 2048 uint4
#define B_U4 (BN*8)           // 1024 uint4
#define STAGE_U4 (A_U4 + B_U4)
#define GNS 3
#define GEMM_SMEM (GNS*STAGE_U4*16)   // 144 KB
#define GTH 256

template<int HALF_OUT>
__device__ __forceinline__ void gemm_core(const __half* __restrict__ A,
                                          const __half* __restrict__ W,
                                          const float* __restrict__ bias,
                                          void* __restrict__ Cv,
                                          int bm, int bn, float cs) {
    extern __shared__ uint4 dsm[];
    const int tid  = threadIdx.x;
    const int wid  = tid >> 5;
    const int lane = tid & 31;
    const int wm   = (wid >> 1) * 64;    // 4 M-groups of 64
    const int wn   = (wid & 1) * 64;     // 2 N-groups of 64
    const int grp  = lane >> 2;
    const int t4   = lane & 3;
    const uint32_t sb = smem_u32(dsm);

    float acc[4][8][4];
    #pragma unroll
    for (int i = 0; i < 4; i++)
        #pragma unroll
        for (int j = 0; j < 8; j++)
            #pragma unroll
            for (int q = 0; q < 4; q++) acc[i][j][q] = 0.f;

    auto load_tile = [&](int it, int buf) {
        uint32_t abase = sb + (uint32_t)(buf*STAGE_U4) * 16u;
        uint32_t bbase = abase + (uint32_t)A_U4 * 16u;
        #pragma unroll
        for (int v = 0; v < 8; ++v) {            // A: 2048 chunks
            int c = v*GTH + tid;
            int r = c >> 3, ch = c & 7;
            cpa16(abase + (uint32_t)(r*8 + (ch ^ (r & 7))) * 16u,
                  (const uint4*)(A + (size_t)(bm + r)*E_ + it*BKH) + ch);
        }
        #pragma unroll
        for (int v = 0; v < 4; ++v) {            // B: 1024 chunks
            int c = v*GTH + tid;
            int r = c >> 3, ch = c & 7;
            cpa16(bbase + (uint32_t)(r*8 + (ch ^ (r & 7))) * 16u,
                  (const uint4*)(W + (size_t)(bn + r)*E_ + it*BKH) + ch);
        }
    };

    load_tile(0, 0); CP_COMMIT();
    load_tile(1, 1); CP_COMMIT();

    for (int it = 0; it < NIT; ++it) {
        if (it + 1 < NIT) { CP_WAIT(1); }
        else              { CP_WAIT(0); }
        __syncthreads();   // all warps finished compute(it-1); tile `it` visible
        if (it + 2 < NIT) {
            load_tile(it + 2, (it + 2) % GNS);   // buf (it-1)%GNS, free after sync
            CP_COMMIT();
        }

        const uint32_t abase = sb + (uint32_t)((it % GNS)*STAGE_U4) * 16u;
        const uint32_t bbase = abase + (uint32_t)A_U4 * 16u;

        // fragment load for one k16 into given buffers
        auto load_frags = [&](int k16, uint32_t fa[4][4], uint32_t fb[8][2]) {
            #pragma unroll
            for (int mf = 0; mf < 4; ++mf) {
                int row = wm + mf*16 + (lane & 15);
                int ch  = k16*2 + (lane >> 4);
                ldsm4(fa[mf][0], fa[mf][1], fa[mf][2], fa[mf][3],
                      abase + (uint32_t)(row*8 + (ch ^ (row & 7))) * 16u);
            }
            #pragma unroll
            for (int np = 0; np < 4; ++np) {
                int row = wn + np*16 + (lane & 7) + ((lane >> 4) & 1)*8;
                int ch  = k16*2 + ((lane >> 3) & 1);
                ldsm4(fb[2*np][0], fb[2*np][1], fb[2*np+1][0], fb[2*np+1][1],
                      bbase + (uint32_t)(row*8 + (ch ^ (row & 7))) * 16u);
            }
        };

        uint32_t fa[2][4][4];
        uint32_t fb[2][8][2];
        load_frags(0, fa[0], fb[0]);
        #pragma unroll
        for (int k16 = 0; k16 < 4; ++k16) {
            int cur = k16 & 1;
            if (k16 < 3) load_frags(k16 + 1, fa[cur ^ 1], fb[cur ^ 1]);
            #pragma unroll
            for (int mf = 0; mf < 4; ++mf)
                #pragma unroll
                for (int nf = 0; nf < 8; ++nf)
                    mma_f16(acc[mf][nf], fa[cur][mf], fb[cur][nf]);
        }
    }

    #pragma unroll
    for (int mf = 0; mf < 4; ++mf) {
        #pragma unroll
        for (int nf = 0; nf < 8; ++nf) {
            int r0 = bm + wm + mf*16 + grp;
            int c0 = bn + wn + nf*8 + t4*2;
            float b0 = bias[c0], b1 = bias[c0 + 1];
            if (HALF_OUT) {
                __half* C = (__half*)Cv;
                *(uint32_t*)(C + (size_t)r0*E_ + c0)     = h2((acc[mf][nf][0] + b0)*cs, (acc[mf][nf][1] + b1)*cs);
                *(uint32_t*)(C + (size_t)(r0+8)*E_ + c0) = h2((acc[mf][nf][2] + b0)*cs, (acc[mf][nf][3] + b1)*cs);
            } else {
                float* C = (float*)Cv;
                float2 v0, v1;
                v0.x = acc[mf][nf][0] + b0; v0.y = acc[mf][nf][1] + b1;
                v1.x = acc[mf][nf][2] + b0; v1.y = acc[mf][nf][3] + b1;
                *(float2*)(C + (size_t)r0*E_ + c0)     = v0;
                *(float2*)(C + (size_t)(r0+8)*E_ + c0) = v1;
            }
        }
    }
}

__global__ __launch_bounds__(GTH, 1) void gemm_qkv(const __half* Aq, const __half* Ak, const __half* Av,
                                                   const __half* Wq, const __half* Wk, const __half* Wv,
                                                   const float* bq, const float* bk, const float* bv,
                                                   __half* Cq, __half* Ck, __half* Cvp) {
    const int z = blockIdx.z;
    const __half* A = (z == 0) ? Aq : (z == 1) ? Ak : Av;
    const __half* W = (z == 0) ? Wq : (z == 1) ? Wk : Wv;
    const float*  bb = (z == 0) ? bq : (z == 1) ? bk : bv;
    __half*       C = (z == 0) ? Cq : (z == 1) ? Ck : Cvp;
    float cs = (z == 0) ? 0.015625f * 1.44269504088896f : 1.f;
    gemm_core<1>(A, W, bb, C, blockIdx.y * BM, blockIdx.x * BN, cs);
}

__global__ __launch_bounds__(GTH, 1) void gemm_out(const __half* __restrict__ A,
                                                   const __half* __restrict__ W,
                                                   const float* __restrict__ bias,
                                                   float* __restrict__ C) {
    gemm_core<0>(A, W, bias, C, blockIdx.y * BM, blockIdx.x * BN, 1.f);
}

// ---------------- fp16 flash attention: 32 q-rows/warp, depth-3 (R14 proven) --
#define KVB_U4 (64*8)
#define ANS 4
#define ATT_SMEM (2*ANS*KVB_U4*16 + ANS*64*4)
#define NT (S_/64)

__global__ __launch_bounds__(256, 1) void attn_h(const __half* __restrict__ Q,
                                                 const __half* __restrict__ K,
                                                 const __half* __restrict__ V,
                                                 const int* __restrict__ mask,
                                                 __half* __restrict__ ctx) {
    extern __shared__ uint4 dsm[];
    uint4* sK = dsm;
    uint4* sV = dsm + ANS*KVB_U4;
    float* mflag = (float*)(dsm + 2*ANS*KVB_U4);

    const int bh = blockIdx.x;
    const int b  = bh >> 3;
    const int h  = bh & 7;
    const int q0 = blockIdx.y * 256;
    const int tid  = threadIdx.x;
    const int wid  = tid >> 5;
    const int lane = tid & 31;
    const int grp  = lane >> 2;
    const int t4   = lane & 3;
    const int row0 = wid * 32;
    const uint32_t sKb = smem_u32(sK);
    const uint32_t sVb = smem_u32(sV);

    const size_t kvbase = (size_t)b*S_*E_ + (size_t)h*D_;

    auto load_kv = [&](int kt, int buf) {
        const int key0 = kt * 64;
        #pragma unroll
        for (int v = 0; v < 2; ++v) {
            int c = tid*2 + v;
            int r = c >> 3, ch = c & 7;
            uint32_t off = (uint32_t)(buf*KVB_U4 + r*8 + (ch ^ (r & 7))) * 16u;
            cpa16(sKb + off, (const uint4*)(K + kvbase + (size_t)(key0 + r)*E_) + ch);
            cpa16(sVb + off, (const uint4*)(V + kvbase + (size_t)(key0 + r)*E_) + ch);
        }
    };

    uint32_t qf[2][4][4];
    const __half* qb = Q + ((size_t)b*S_ + q0 + row0)*E_ + h*D_;
    #pragma unroll
    for (int mf = 0; mf < 2; ++mf) {
        #pragma unroll
        for (int k16 = 0; k16 < 4; ++k16) {
            qf[mf][k16][0] = *(const uint32_t*)(qb + (size_t)(mf*16 + grp)*E_     + k16*16 + 2*t4);
            qf[mf][k16][1] = *(const uint32_t*)(qb + (size_t)(mf*16 + grp + 8)*E_ + k16*16 + 2*t4);
            qf[mf][k16][2] = *(const uint32_t*)(qb + (size_t)(mf*16 + grp)*E_     + k16*16 + 2*t4 + 8);
            qf[mf][k16][3] = *(const uint32_t*)(qb + (size_t)(mf*16 + grp + 8)*E_ + k16*16 + 2*t4 + 8);
        }
    }

    float oacc[2][8][4];
    #pragma unroll
    for (int mf = 0; mf < 2; mf++)
        #pragma unroll
        for (int nf = 0; nf < 8; nf++)
            #pragma unroll
            for (int c = 0; c < 4; c++) oacc[mf][nf][c] = 0.f;
    float dacc[2][4] = {{0.f,0.f,0.f,0.f},{0.f,0.f,0.f,0.f}};
    const uint32_t ones2[2] = {0x3C003C00u, 0x3C003C00u};

    // prologue: 3 tiles in flight (depth 3)
    load_kv(0, 0); CP_COMMIT();
    load_kv(1, 1); CP_COMMIT();
    load_kv(2, 2); CP_COMMIT();
    int mq0 = 0, mq1 = 0, mq2 = 0;
    if (tid < 64) {
        mq0 = mask[b*S_ + tid];
        mq1 = mask[b*S_ + 64 + tid];
        mq2 = mask[b*S_ + 128 + tid];
    }

    for (int kt = 0; kt < NT; ++kt) {
        if (tid < 64) mflag[(kt % ANS)*64 + tid] = mq0 ? 0.f : -60000.f;
        mq0 = mq1; mq1 = mq2;
        if (kt + 2 < NT)      { CP_WAIT(2); }
        else if (kt + 1 < NT) { CP_WAIT(1); }
        else                  { CP_WAIT(0); }
        __syncthreads();   // tile kt visible; all warps finished compute(kt-1)
        if (kt + 3 < NT) {
            load_kv(kt + 3, (kt + 3) % ANS);   // buf (kt-1)%ANS, free after sync
            CP_COMMIT();
            if (tid < 64) mq2 = mask[b*S_ + (kt + 3)*64 + tid];
        }

        const uint32_t koff = (uint32_t)((kt % ANS)*KVB_U4) * 16u;
        const float* mf_ = mflag + (kt % ANS)*64;

        float sacc[2][8][4];
        #pragma unroll
        for (int nf = 0; nf < 8; nf++) {
            float2 mo = *(const float2*)&mf_[nf*8 + 2*t4];
            #pragma unroll
            for (int mf = 0; mf < 2; mf++) {
                sacc[mf][nf][0] = mo.x; sacc[mf][nf][1] = mo.y;
                sacc[mf][nf][2] = mo.x; sacc[mf][nf][3] = mo.y;
            }
        }
        #pragma unroll
        for (int k16 = 0; k16 < 4; ++k16) {
            #pragma unroll
            for (int np = 0; np < 4; ++np) {
                uint32_t b0, b1, b2, b3;
                int row = np*16 + (lane & 7) + ((lane >> 4) & 1)*8;
                int ch  = k16*2 + ((lane >> 3) & 1);
                ldsm4(b0, b1, b2, b3, sKb + koff + (uint32_t)(row*8 + (ch ^ (row & 7))) * 16u);
                uint32_t bb0[2] = {b0, b1}, bb1[2] = {b2, b3};
                #pragma unroll
                for (int mf = 0; mf < 2; mf++) {
                    mma_f16(sacc[mf][2*np],   qf[mf][k16], bb0);
                    mma_f16(sacc[mf][2*np+1], qf[mf][k16], bb1);
                }
            }
        }

        uint32_t pf[2][4][4];
        #pragma unroll
        for (int mf = 0; mf < 2; mf++)
            #pragma unroll
            for (int nf = 0; nf < 8; nf++) {
                pf[mf][nf >> 1][(nf & 1) * 2]     = ex2h2(sacc[mf][nf][0], sacc[mf][nf][1]);
                pf[mf][nf >> 1][(nf & 1) * 2 + 1] = ex2h2(sacc[mf][nf][2], sacc[mf][nf][3]);
            }

        #pragma unroll
        for (int k16 = 0; k16 < 4; ++k16) {
            #pragma unroll
            for (int np = 0; np < 4; ++np) {
                uint32_t b0, b1, b2, b3;
                int row = k16*16 + (lane & 7) + ((lane >> 3) & 1)*8;
                int ch  = np*2 + ((lane >> 4) & 1);
                ldsm4t(b0, b1, b2, b3, sVb + koff + (uint32_t)(row*8 + (ch ^ (row & 7))) * 16u);
                uint32_t bb0[2] = {b0, b1}, bb1[2] = {b2, b3};
                #pragma unroll
                for (int mf = 0; mf < 2; mf++) {
                    mma_f16(oacc[mf][2*np],   pf[mf][k16], bb0);
                    mma_f16(oacc[mf][2*np+1], pf[mf][k16], bb1);
                }
            }
            #pragma unroll
            for (int mf = 0; mf < 2; mf++)
                mma_f16(dacc[mf], pf[mf][k16], ones2);
        }
    }

    #pragma unroll
    for (int mf = 0; mf < 2; mf++) {
        float i0 = 1.f / dacc[mf][0], i1 = 1.f / dacc[mf][2];
        __half* op = ctx + ((size_t)b*S_ + q0 + row0 + mf*16)*E_ + h*D_;
        #pragma unroll
        for (int nf = 0; nf < 8; nf++) {
            int c0 = nf*8 + 2*t4;
            *(uint32_t*)(op + (size_t)grp*E_ + c0)     = h2(oacc[mf][nf][0]*i0, oacc[mf][nf][1]*i0);
            *(uint32_t*)(op + (size_t)(grp+8)*E_ + c0) = h2(oacc[mf][nf][2]*i1, oacc[mf][nf][3]*i1);
        }
    }
}

// ---------------- launch ----------------
extern "C" void kernel_launch(void* const* d_in, const int* in_sizes, int n_in,
                              void* d_out, int out_size) {
    const float* q      = (const float*)d_in[0];
    const float* k      = (const float*)d_in[1];
    const float* v      = (const float*)d_in[2];
    const float* Wq     = (const float*)d_in[3];
    const float* bq     = (const float*)d_in[4];
    const float* Wk     = (const float*)d_in[5];
    const float* bk     = (const float*)d_in[6];
    const float* Wv_sh  = (const float*)d_in[7];
    const float* Wv_sp  = (const float*)d_in[8];
    const float* bv_sh  = (const float*)d_in[9];
    const float* bv_sp  = (const float*)d_in[10];
    const float* Wo_sh  = (const float*)d_in[11];
    const float* Wo_sp  = (const float*)d_in[12];
    const float* bo_sh  = (const float*)d_in[13];
    const float* bo_sp  = (const float*)d_in[14];
    const int*   mask   = (const int*)d_in[15];
    const int*   lang   = (const int*)d_in[16];

    void *pqh, *pkh, *pvh, *pQh, *pKh, *pVh, *pctx;
    void *pWq, *pWk, *pWv, *pWo, *pbv, *pbo;
    cudaGetSymbolAddress(&pqh, g_qh);
    cudaGetSymbolAddress(&pkh, g_kh);
    cudaGetSymbolAddress(&pvh, g_vh);
    cudaGetSymbolAddress(&pQh, g_Qh);
    cudaGetSymbolAddress(&pKh, g_Kh);
    cudaGetSymbolAddress(&pVh, g_Vh);
    cudaGetSymbolAddress(&pctx, g_ctxh);
    cudaGetSymbolAddress(&pWq, g_Wqh);
    cudaGetSymbolAddress(&pWk, g_Wkh);
    cudaGetSymbolAddress(&pWv, g_Wvh);
    cudaGetSymbolAddress(&pWo, g_Woh);
    cudaGetSymbolAddress(&pbv, g_bv);
    cudaGetSymbolAddress(&pbo, g_bo);

    static int attr_set = 0;
    if (!attr_set) {
        cudaFuncSetAttribute(gemm_qkv, cudaFuncAttributeMaxDynamicSharedMemorySize, GEMM_SMEM);
        cudaFuncSetAttribute(gemm_out, cudaFuncAttributeMaxDynamicSharedMemorySize, GEMM_SMEM);
        cudaFuncSetAttribute(attn_h,   cudaFuncAttributeMaxDynamicSharedMemorySize, ATT_SMEM);
        attr_set = 1;
    }

    prep_all<<<4096 + 256, 256>>>(q, k, v, Wq, Wk, Wv_sh, Wv_sp, Wo_sh, Wo_sp,
                                  bv_sh, bv_sp, bo_sh, bo_sp, lang);

    dim3 gq(E_/BN, M_/BM, 3);   // (4, 64, 3)
    gemm_qkv<<<gq, GTH, GEMM_SMEM>>>((const __half*)pqh, (const __half*)pkh, (const __half*)pvh,
                                     (const __half*)pWq, (const __half*)pWk, (const __half*)pWv,
                                     bq, bk, (const float*)pbv,
                                     (__half*)pQh, (__half*)pKh, (__half*)pVh);

    attn_h<<<dim3(B_*H_, S_/256), 256, ATT_SMEM>>>((const __half*)pQh, (const __half*)pKh,
                                                   (const __half*)pVh, mask, (__half*)pctx);

    dim3 gg(E_/BN, M_/BM);   // (4, 64)
    gemm_out<<<gg, GTH, GEMM_SMEM>>>((const __half*)pctx, (const __half*)pWo,
                                     (const float*)pbo, (float*)d_out);
}